// round 8
// baseline (speedup 1.0000x reference)
#include <cuda_runtime.h>
#include <cstdint>
#include <math.h>

// Problem dims (fixed by the reference)
static constexpr int B_ = 16;
static constexpr int C_ = 256;
static constexpr int N_ = 4096;
static constexpr int M_ = 1024;
static constexpr float EPS_ = 1e-5f;

// ---------------- scratch (static device globals; no allocation) ----------
__device__ float g_mean[B_ * C_];
__device__ float g_score[B_ * N_];
__device__ int   g_idx[B_ * 2 * M_];
__device__ float g_Xs[(size_t)B_ * C_ * M_];
__device__ float g_Xg[(size_t)B_ * C_ * M_];
__device__ float g_Q[(size_t)B_ * N_ * C_];   // Q^T: [n][d], d contiguous
__device__ float g_K[(size_t)B_ * M_ * C_];   // K^T: [m][d], d contiguous
__device__ float g_WV[(size_t)B_ * C_ * M_];  // (Wo@Wv)@Xctx + Wo@bv
__device__ float g_S[(size_t)B_ * N_ * M_];   // E = exp(scores)
__device__ float g_ys[(size_t)B_ * C_ * N_];
__device__ float g_yg[(size_t)B_ * C_ * N_];
__device__ float g_Z[(size_t)B_ * C_ * N_];
__device__ float g_den[2 * B_ * N_];          // softmax denominators (2 attns)
__device__ float g_Wow[2 * C_ * C_];          // Wo @ Wv per attention
__device__ float g_bov[2 * C_];               // Wo @ bv per attention
__device__ float g_mu[C_];
__device__ float g_rstd[C_];

// ---------------- helpers --------------------------------------------------
// mma.tf32 reads the tf32 subset of the b32 register (truncation).
__device__ __forceinline__ void mma_tf32(float* c, const uint32_t* a, const uint32_t* b) {
    asm volatile(
        "mma.sync.aligned.m16n8k8.row.col.f32.tf32.tf32.f32 "
        "{%0,%1,%2,%3}, {%4,%5,%6,%7}, {%8,%9}, {%0,%1,%2,%3};"
        : "+f"(c[0]), "+f"(c[1]), "+f"(c[2]), "+f"(c[3])
        : "r"(a[0]), "r"(a[1]), "r"(a[2]), "r"(a[3]), "r"(b[0]), "r"(b[1]));
}
__device__ __forceinline__ void ldsm_x4(uint32_t& r0, uint32_t& r1,
                                        uint32_t& r2, uint32_t& r3, uint32_t addr) {
    asm volatile("ldmatrix.sync.aligned.m8n8.x4.shared.b16 {%0,%1,%2,%3}, [%4];"
                 : "=r"(r0), "=r"(r1), "=r"(r2), "=r"(r3) : "r"(addr));
}
__device__ __forceinline__ uint32_t smem_u32(const void* p) {
    uint32_t a;
    asm("{ .reg .u64 t; cvta.to.shared.u64 t, %1; cvt.u32.u64 %0, t; }"
        : "=r"(a) : "l"(p));
    return a;
}
__device__ __forceinline__ void cp16(uint32_t saddr, const float* g) {
    asm volatile("cp.async.cg.shared.global [%0], [%1], 16;" :: "r"(saddr), "l"(g));
}

// ================== pipelined warp-MMA tf32 generic strided GEMM ==========
// Normal: D[i,j] = scale*acc [*colscale[j]] + scale*(bias[i]+cbias[j])
//                  [+addend] [+D_old]
// Exp mode (rowsum != nullptr):
//   D[i,j] = exp(acc[i,j]); rowsum[i] += sum_j D[i,j] (atomic)
// A(i,k) = A[i*As0 + k*As1]; B(j,k) = B[j*Bs0 + k*Bs1]; one stride is 1.
// k-contig operands use ldmatrix; i/j-contig use padded LDS.
// Block tile 128x128, 4 warps (64x64 each), BK=32. Md,Nd %128; Kd %32.
#define BM 128
#define BN 128
#define BK 32
#define SKC 36   // smem row stride (words), k-contig layout [i][k]
#define SIC 136  // smem row stride (words), i-contig layout [k][i]
#define OPW 4608 // words per operand per stage = max(128*36, 32*136)

__device__ __forceinline__ void stage_tile(const float* __restrict__ src,
                                           long s0, long s1, int kc,
                                           uint32_t sbase, int t0, int kt, int tid) {
    if (kc) {  // k contiguous -> smem [i][k], stride SKC
#pragma unroll
        for (int it = 0; it < 8; it++) {
            int q = tid + it * 128;
            int row = q >> 3, kq = (q & 7) << 2;
            cp16(sbase + (uint32_t)(row * SKC + kq) * 4u,
                 src + (long)(t0 + row) * s0 + kt + kq);
        }
    } else {   // i contiguous -> smem [k][i], stride SIC
#pragma unroll
        for (int it = 0; it < 8; it++) {
            int q = tid + it * 128;
            int kr = q >> 5, iq = (q & 31) << 2;
            cp16(sbase + (uint32_t)(kr * SIC + iq) * 4u,
                 src + (long)(t0 + iq) + (long)(kt + kr) * s1);
        }
    }
}

__global__ void __launch_bounds__(128, 2)
tc_gemm_kernel(const float* __restrict__ A, long Ab, long As0, long As1,
               const float* __restrict__ Bp, long Bb, long Bs0, long Bs1,
               float* __restrict__ Cp, long Cb, long Cs0,
               const float* __restrict__ bias,
               const float* __restrict__ cbias,
               const float* __restrict__ addend, long Addb,
               float* rowsum, long Rsb,
               const float* __restrict__ colscale, long Csb,
               float scale, int accumulate, int Kd) {
    extern __shared__ uint32_t sm[];

    const int tid = threadIdx.x;
    const int wid = tid >> 5;
    const int lane = tid & 31;
    const int g = lane >> 2;
    const int t4 = lane & 3;
    const int wm = wid & 1;    // warp row (64 rows)
    const int wn = wid >> 1;   // warp col (64 cols)
    const int tr = lane & 7;   // ldmatrix row within 8
    const int tq = lane >> 3;  // ldmatrix quad (matrix select)

    const int aKc = (As1 == 1);
    const int bKc = (Bs1 == 1);

    const int bz = blockIdx.z;
    A += (size_t)bz * Ab;
    Bp += (size_t)bz * Bb;
    Cp += (size_t)bz * Cb;
    if (addend) addend += (size_t)bz * Addb;
    if (rowsum) rowsum += (size_t)bz * Rsb;
    if (colscale) colscale += (size_t)bz * Csb;

    const int i0 = blockIdx.y * BM;
    const int j0 = blockIdx.x * BN;

    const uint32_t smbase = smem_u32(sm);
    // ldmatrix per-thread base byte offsets within a tile
    // A quads: {rows +0, rows +8, cols +4 rows +0, cols +4 rows +8}
    const uint32_t aOff = (uint32_t)((wm * 64 + (tq & 1) * 8 + tr) * SKC + (tq >> 1) * 4) * 4u;
    // B quads: {nt rows +0 k, nt rows +0 k+4, nt+1 rows (+8) k, nt+1 rows k+4}
    const uint32_t bOff = (uint32_t)((wn * 64 + (tq >> 1) * 8 + tr) * SKC + (tq & 1) * 4) * 4u;

    float acc[4][8][4];
#pragma unroll
    for (int a = 0; a < 4; a++)
#pragma unroll
        for (int b = 0; b < 8; b++)
#pragma unroll
            for (int c = 0; c < 4; c++) acc[a][b][c] = 0.f;

    const int nch = Kd >> 5;

    stage_tile(A, As0, As1, aKc, smbase, i0, 0, tid);
    stage_tile(Bp, Bs0, Bs1, bKc, smbase + OPW * 4u, j0, 0, tid);
    asm volatile("cp.async.commit_group;" ::: "memory");

    for (int ch = 0; ch < nch; ch++) {
        if (ch + 1 < nch) {
            uint32_t sb = smbase + (uint32_t)(((ch + 1) & 1) * 2 * OPW) * 4u;
            stage_tile(A, As0, As1, aKc, sb, i0, (ch + 1) * BK, tid);
            stage_tile(Bp, Bs0, Bs1, bKc, sb + OPW * 4u, j0, (ch + 1) * BK, tid);
        }
        asm volatile("cp.async.commit_group;" ::: "memory");
        asm volatile("cp.async.wait_group 1;" ::: "memory");
        __syncthreads();

        const uint32_t* sA = sm + (ch & 1) * 2 * OPW;
        const uint32_t* sB = sA + OPW;
        const uint32_t sAu = smbase + (uint32_t)((ch & 1) * 2 * OPW) * 4u;
        const uint32_t sBu = sAu + OPW * 4u;

#pragma unroll
        for (int ks = 0; ks < BK; ks += 8) {
            uint32_t af[4][4];
            if (aKc) {
#pragma unroll
                for (int mt = 0; mt < 4; mt++)
                    ldsm_x4(af[mt][0], af[mt][1], af[mt][2], af[mt][3],
                            sAu + aOff + (uint32_t)(mt * 16 * SKC + ks) * 4u);
            } else {
#pragma unroll
                for (int mt = 0; mt < 4; mt++) {
                    int rb = wm * 64 + mt * 16 + g;
                    af[mt][0] = sA[(ks + t4    ) * SIC + rb    ];
                    af[mt][1] = sA[(ks + t4    ) * SIC + rb + 8];
                    af[mt][2] = sA[(ks + t4 + 4) * SIC + rb    ];
                    af[mt][3] = sA[(ks + t4 + 4) * SIC + rb + 8];
                }
            }
            uint32_t bf[8][2];
            if (bKc) {
#pragma unroll
                for (int p = 0; p < 4; p++)
                    ldsm_x4(bf[2 * p][0], bf[2 * p][1], bf[2 * p + 1][0], bf[2 * p + 1][1],
                            sBu + bOff + (uint32_t)(p * 16 * SKC + ks) * 4u);
            } else {
#pragma unroll
                for (int nt = 0; nt < 8; nt++) {
                    int cb = wn * 64 + nt * 8 + g;
                    bf[nt][0] = sB[(ks + t4    ) * SIC + cb];
                    bf[nt][1] = sB[(ks + t4 + 4) * SIC + cb];
                }
            }
#pragma unroll
            for (int mt = 0; mt < 4; mt++)
#pragma unroll
                for (int nt = 0; nt < 8; nt++)
                    mma_tf32(acc[mt][nt], af[mt], bf[nt]);
        }
        __syncthreads();
    }

    // ---- epilogue ----
    if (rowsum) {
#pragma unroll
        for (int mt = 0; mt < 4; mt++) {
#pragma unroll
            for (int half = 0; half < 2; half++) {
                int i = i0 + wm * 64 + mt * 16 + g + half * 8;
                float rs = 0.f;
#pragma unroll
                for (int nt = 0; nt < 8; nt++) {
                    int j = j0 + wn * 64 + nt * 8 + t4 * 2;
                    float e0 = __expf(acc[mt][nt][half * 2 + 0]);
                    float e1 = __expf(acc[mt][nt][half * 2 + 1]);
                    *(float2*)(Cp + (long)i * Cs0 + j) = make_float2(e0, e1);
                    rs += e0 + e1;
                }
                rs += __shfl_xor_sync(0xffffffffu, rs, 1);
                rs += __shfl_xor_sync(0xffffffffu, rs, 2);
                if (t4 == 0) atomicAdd(&rowsum[i], rs);
            }
        }
        return;
    }
#pragma unroll
    for (int mt = 0; mt < 4; mt++) {
#pragma unroll
        for (int half = 0; half < 2; half++) {
            int i = i0 + wm * 64 + mt * 16 + g + half * 8;
            float bi = bias ? scale * bias[i] : 0.f;
#pragma unroll
            for (int nt = 0; nt < 8; nt++) {
                int j = j0 + wn * 64 + nt * 8 + t4 * 2;
                long off = (long)i * Cs0 + j;
                float2 v;
                v.x = scale * acc[mt][nt][half * 2 + 0];
                v.y = scale * acc[mt][nt][half * 2 + 1];
                if (colscale) {
                    v.x *= colscale[j];
                    v.y *= colscale[j + 1];
                }
                v.x += bi; v.y += bi;
                if (cbias) {
                    v.x += scale * cbias[j];
                    v.y += scale * cbias[j + 1];
                }
                if (addend) {
                    float2 a2 = *(const float2*)(addend + off);
                    v.x += a2.x; v.y += a2.y;
                }
                if (accumulate) {
                    float2 o2 = *(const float2*)(Cp + off);
                    v.x += o2.x; v.y += o2.y;
                }
                *(float2*)(Cp + off) = v;
            }
        }
    }
}

// ---------------- bov = Wo @ bv (per attention) ----------------
__global__ void bov_kernel(const float* __restrict__ Wo,
                           const float* __restrict__ bv, int a) {
    int e = threadIdx.x;  // 256 threads
    const float* row = Wo + e * C_;
    float s = 0.f;
#pragma unroll 8
    for (int c = 0; c < C_; c++) s += row[c] * bv[c];
    g_bov[a * C_ + e] = s;
}

// ---------------- invert softmax denominators in place ----------------
__global__ void invden_kernel(int a) {
    int i = blockIdx.x * 256 + threadIdx.x;
    g_den[a * B_ * N_ + i] = 1.f / g_den[a * B_ * N_ + i];
}

// ---------------- mean over N per (b,c) ----------------
__global__ void mean_kernel(const float* __restrict__ x) {
    int bc = blockIdx.x;
    const float* row = x + (size_t)bc * N_;
    float s = 0.f;
    for (int n = threadIdx.x; n < N_; n += 256) s += row[n];
    __shared__ float sh[256];
    sh[threadIdx.x] = s;
    __syncthreads();
    for (int o = 128; o > 0; o >>= 1) {
        if (threadIdx.x < o) sh[threadIdx.x] += sh[threadIdx.x + o];
        __syncthreads();
    }
    if (threadIdx.x == 0) g_mean[bc] = sh[0] * (1.f / N_);
}

// ---------------- variation score per (b,n); also zeros denominators ------
__global__ void score_kernel(const float* __restrict__ x) {
    int b = blockIdx.y;
    int n = blockIdx.x * 256 + threadIdx.x;
    const float* xb = x + (size_t)b * C_ * N_;
    const float* mb = g_mean + b * C_;
    float acc = 0.f;
#pragma unroll 4
    for (int c = 0; c < C_; c++) {
        float v = xb[(size_t)c * N_ + n] - mb[c];
        acc += v * v;
    }
    int gi = b * N_ + n;
    g_score[gi] = acc;
    g_den[gi] = 0.f;
    g_den[B_ * N_ + gi] = 0.f;
}

// ---------------- per-batch bitonic full sort ----------------
__global__ void topk_kernel() {
    __shared__ float sk[N_];
    __shared__ int   sv[N_];
    int b = blockIdx.x;
    int t = threadIdx.x;
    for (int i = t; i < N_; i += 1024) {
        sk[i] = g_score[b * N_ + i];
        sv[i] = i;
    }
    __syncthreads();
    for (int k = 2; k <= N_; k <<= 1) {
        for (int j = k >> 1; j > 0; j >>= 1) {
            for (int i = t; i < N_; i += 1024) {
                int ixj = i ^ j;
                if (ixj > i) {
                    bool up = ((i & k) == 0);
                    float a = sk[i], c = sk[ixj];
                    bool sw = up ? (a > c) : (a < c);
                    if (sw) {
                        sk[i] = c; sk[ixj] = a;
                        int tv = sv[i]; sv[i] = sv[ixj]; sv[ixj] = tv;
                    }
                }
            }
            __syncthreads();
        }
    }
    if (t < M_) {
        g_idx[b * 2 * M_ + t]      = sv[N_ - 1 - t];  // sharp
        g_idx[b * 2 * M_ + M_ + t] = sv[t];           // gentle
    }
}

// ---------------- gather selected columns (both sets in one launch) -------
__global__ void gather_kernel(const float* __restrict__ x) {
    int m = blockIdx.x * 256 + threadIdx.x;
    int c = blockIdx.y;
    int b = blockIdx.z >> 1;
    int which = blockIdx.z & 1;
    const int* idx = g_idx + b * 2 * M_ + which * M_;
    float v = x[((size_t)b * C_ + c) * N_ + idx[m]];
    float* dst = which ? g_Xg : g_Xs;
    dst[((size_t)b * C_ + c) * M_ + m] = v;
}

// ---------------- per-channel batch stats ----------------
__global__ void chanstat_kernel() {
    int d = blockIdx.x;
    float s = 0.f, s2 = 0.f;
    for (int b = 0; b < B_; b++) {
        const float* row = g_Z + ((size_t)b * C_ + d) * N_;
        for (int n = threadIdx.x; n < N_; n += 256) {
            float v = row[n];
            s += v;
            s2 += v * v;
        }
    }
    __shared__ float shs[256];
    __shared__ float shq[256];
    shs[threadIdx.x] = s;
    shq[threadIdx.x] = s2;
    __syncthreads();
    for (int o = 128; o > 0; o >>= 1) {
        if (threadIdx.x < o) {
            shs[threadIdx.x] += shs[threadIdx.x + o];
            shq[threadIdx.x] += shq[threadIdx.x + o];
        }
        __syncthreads();
    }
    if (threadIdx.x == 0) {
        const float invBN = 1.f / (float)(B_ * N_);
        float mu = shs[0] * invBN;
        float var = shq[0] * invBN - mu * mu;
        g_mu[d] = mu;
        g_rstd[d] = rsqrtf(var + EPS_);
    }
}

// ---------------- BN + ReLU ----------------
__global__ void bnrelu_kernel(const float* __restrict__ gamma,
                              const float* __restrict__ beta,
                              float* __restrict__ out) {
    size_t i = (size_t)blockIdx.x * 256 + threadIdx.x;
    int d = (int)((i / N_) % C_);
    float v = (g_Z[i] - g_mu[d]) * g_rstd[d] * gamma[d] + beta[d];
    out[i] = fmaxf(v, 0.f);
}

// ---------------- host side ------------------------------------------------
static float* sym_f(const void* s) {
    void* p = nullptr;
    cudaGetSymbolAddress(&p, s);
    return (float*)p;
}

static constexpr int GEMM_SMEM = 4 * OPW * 4;  // 73728 bytes

static void launch_tc(const float* A, long Ab, long As0, long As1,
                      const float* Bp, long Bb, long Bs0, long Bs1,
                      float* Cp, long Cb, long Cs0,
                      const float* bias, const float* cbias,
                      const float* addend, long Addb,
                      float* rowsum, long Rsb,
                      const float* colscale, long Csb,
                      float scale, int accumulate, int Md, int Nd, int Kd,
                      int nbatch) {
    dim3 grid(Nd / BN, Md / BM, nbatch);
    tc_gemm_kernel<<<grid, 128, GEMM_SMEM>>>(
        A, Ab, As0, As1, Bp, Bb, Bs0, Bs1, Cp, Cb, Cs0,
        bias, cbias, addend, Addb, rowsum, Rsb, colscale, Csb,
        scale, accumulate, Kd);
}

extern "C" void kernel_launch(void* const* d_in, const int* in_sizes, int n_in,
                              void* d_out, int out_size) {
    static bool attr_done = false;
    if (!attr_done) {
        cudaFuncSetAttribute(tc_gemm_kernel,
                             cudaFuncAttributeMaxDynamicSharedMemorySize, GEMM_SMEM);
        attr_done = true;
    }

    const float* P[24];
    int p = 0;
    for (int i = 0; i < n_in && p < 24; i++) {
        if (in_sizes[i] == 1) continue;  // num_select scalar
        P[p++] = (const float*)d_in[i];
    }
    const float* x = P[0];
    const float* Wq[2] = {P[1], P[9]};
    const float* bq[2] = {P[2], P[10]};
    const float* Wk[2] = {P[3], P[11]};
    const float* bk[2] = {P[4], P[12]};
    const float* Wv[2] = {P[5], P[13]};
    const float* bv[2] = {P[6], P[14]};
    const float* Wo[2] = {P[7], P[15]};
    const float* bo[2] = {P[8], P[16]};
    const float* Wf = P[17];
    const float* bf = P[18];
    const float* gamma = P[19];
    const float* beta = P[20];
    float* out = (float*)d_out;

    float* Q   = sym_f(g_Q);
    float* K   = sym_f(g_K);
    float* WV  = sym_f(g_WV);
    float* S   = sym_f(g_S);
    float* Xs  = sym_f(g_Xs);
    float* Xg  = sym_f(g_Xg);
    float* ys  = sym_f(g_ys);
    float* yg  = sym_f(g_yg);
    float* Z   = sym_f(g_Z);
    float* den = sym_f(g_den);
    float* Wow = sym_f(g_Wow);
    float* bov = sym_f(g_bov);

    const long xB = (long)C_ * N_;
    const long cM = (long)C_ * M_;
    const long sB = (long)N_ * M_;

    // 1) geometry disentangle
    mean_kernel<<<B_ * C_, 256>>>(x);
    score_kernel<<<dim3(N_ / 256, B_), 256>>>(x);  // also zeros g_den
    topk_kernel<<<B_, 1024>>>();
    gather_kernel<<<dim3(M_ / 256, C_, 2 * B_), 256>>>(x);

    // 2) two cross-attentions
    for (int a = 0; a < 2; a++) {
        const float* Xctx = (a == 0) ? Xs : Xg;
        float* ybuf = (a == 0) ? ys : yg;
        float* dena = den + a * B_ * N_;
        float* Wowa = Wow + a * C_ * C_;
        float* bova = bov + a * C_;

        // Kt[m,d] = sum_c Xctx[c,m] Wk[d,c] + bk[d]  (i=m i-contig A; B k-contig)
        launch_tc(Xctx, cM, 1, M_, Wk[a], 0, C_, 1, K, (long)M_ * C_, C_,
                  nullptr, bk[a], nullptr, 0, nullptr, 0, nullptr, 0,
                  1.f, 0, M_, C_, C_, B_);
        // Qt[n,d] = (sum_c x[c,n] Wq[d,c] + bq[d])/16
        launch_tc(x, xB, 1, N_, Wq[a], 0, C_, 1, Q, (long)N_ * C_, C_,
                  nullptr, bq[a], nullptr, 0, nullptr, 0, nullptr, 0,
                  0.0625f, 0, N_, C_, C_, B_);
        // Wow[e,c2] = sum_c Wo[e,c] Wv[c,c2]
        launch_tc(Wo[a], 0, C_, 1, Wv[a], 0, 1, C_, Wowa, 0, C_,
                  nullptr, nullptr, nullptr, 0, nullptr, 0, nullptr, 0,
                  1.f, 0, C_, C_, C_, 1);
        bov_kernel<<<1, 256>>>(Wo[a], bv[a], a);
        // E[n,m] = exp(sum_d Qt[n,d] Kt[m,d]); den += row sums  (both k-contig)
        launch_tc(Q, (long)N_ * C_, C_, 1, K, (long)M_ * C_, C_, 1, S, sB, M_,
                  nullptr, nullptr, nullptr, 0, dena, N_, nullptr, 0,
                  1.f, 0, N_, M_, C_, B_);
        invden_kernel<<<(B_ * N_) / 256, 256>>>(a);
        // WV[e,m] = Wow@Xctx + bov
        launch_tc(Wowa, 0, C_, 1, Xctx, cM, 1, M_, WV, cM, M_,
                  bova, nullptr, nullptr, 0, nullptr, 0, nullptr, 0,
                  1.f, 0, C_, M_, C_, B_);
        // y[e,n] = (sum_m WV[e,m] E[n,m]) * invden[b,n] + bo[e] + x[e,n]
        launch_tc(WV, cM, M_, 1, S, sB, M_, 1, ybuf, xB, N_,
                  bo[a], nullptr, x, xB, nullptr, 0, dena, N_,
                  1.f, 0, C_, N_, M_, B_);
    }

    // 3) fuse: Z = Wf[:, :C]@ys + Wf[:, C:]@yg + bf
    launch_tc(Wf, 0, 2 * C_, 1, ys, xB, 1, N_, Z, xB, N_,
              nullptr, nullptr, nullptr, 0, nullptr, 0, nullptr, 0,
              1.f, 0, C_, N_, C_, B_);
    launch_tc(Wf + C_, 0, 2 * C_, 1, yg, xB, 1, N_, Z, xB, N_,
              bf, nullptr, nullptr, 0, nullptr, 0, nullptr, 0,
              1.f, 1, C_, N_, C_, B_);

    // 4) batch-norm (training stats) + ReLU
    chanstat_kernel<<<C_, 256>>>();
    bnrelu_kernel<<<(B_ * C_ * N_) / 256, 256>>>(gamma, beta, out);
}

// round 9
// speedup vs baseline: 1.0550x; 1.0550x over previous
#include <cuda_runtime.h>
#include <cstdint>
#include <math.h>

// Problem dims (fixed by the reference)
static constexpr int B_ = 16;
static constexpr int C_ = 256;
static constexpr int N_ = 4096;
static constexpr int M_ = 1024;
static constexpr float EPS_ = 1e-5f;

// ---------------- scratch (static device globals; no allocation) ----------
__device__ float g_mean[B_ * C_];
__device__ float g_score[B_ * N_];
__device__ int   g_idx[B_ * 2 * M_];
__device__ float g_Xs[(size_t)B_ * C_ * M_];
__device__ float g_Xg[(size_t)B_ * C_ * M_];
__device__ float g_Q[(size_t)B_ * N_ * C_];   // Q^T: [n][d], d contiguous
__device__ float g_K[(size_t)B_ * M_ * C_];   // K^T: [m][d], d contiguous
__device__ float g_WV[(size_t)B_ * C_ * M_];  // (Wo@Wv)@Xctx + Wo@bv
__device__ float g_S[(size_t)B_ * N_ * M_];   // E = exp(scores)
__device__ float g_ys[(size_t)B_ * C_ * N_];
__device__ float g_yg[(size_t)B_ * C_ * N_];
__device__ float g_Z[(size_t)B_ * C_ * N_];
__device__ float g_den[2 * B_ * N_];          // softmax denominators (2 attns)
__device__ float g_Wow[2 * C_ * C_];          // Wo @ Wv per attention
__device__ float g_bov[2 * C_];               // Wo @ bv per attention
__device__ float g_mu[C_];
__device__ float g_rstd[C_];

// ---------------- helpers --------------------------------------------------
// mma.tf32 reads the tf32 subset of the b32 register (truncation).
__device__ __forceinline__ void mma_tf32(float* c, const uint32_t* a, const uint32_t* b) {
    asm volatile(
        "mma.sync.aligned.m16n8k8.row.col.f32.tf32.tf32.f32 "
        "{%0,%1,%2,%3}, {%4,%5,%6,%7}, {%8,%9}, {%0,%1,%2,%3};"
        : "+f"(c[0]), "+f"(c[1]), "+f"(c[2]), "+f"(c[3])
        : "r"(a[0]), "r"(a[1]), "r"(a[2]), "r"(a[3]), "r"(b[0]), "r"(b[1]));
}
__device__ __forceinline__ void ldsm_x4(uint32_t& r0, uint32_t& r1,
                                        uint32_t& r2, uint32_t& r3, uint32_t addr) {
    asm volatile("ldmatrix.sync.aligned.m8n8.x4.shared.b16 {%0,%1,%2,%3}, [%4];"
                 : "=r"(r0), "=r"(r1), "=r"(r2), "=r"(r3) : "r"(addr));
}
__device__ __forceinline__ uint32_t smem_u32(const void* p) {
    uint32_t a;
    asm("{ .reg .u64 t; cvta.to.shared.u64 t, %1; cvt.u32.u64 %0, t; }"
        : "=r"(a) : "l"(p));
    return a;
}
__device__ __forceinline__ void cp16(uint32_t saddr, const float* g) {
    asm volatile("cp.async.cg.shared.global [%0], [%1], 16;" :: "r"(saddr), "l"(g));
}

// ================== pipelined warp-MMA tf32 generic strided GEMM ==========
// Normal: D[i,j] = scale*acc [*colscale[j]] + scale*(bias[i]+cbias[j])
//                  [+addend] [+D_old]
// Exp mode (rowsum != nullptr):
//   D[i,j] = exp(acc[i,j]); rowsum[i] += sum_j D[i,j] (atomic)
// A(i,k) = A[i*As0 + k*As1]; B(j,k) = B[j*Bs0 + k*Bs1]; one stride is 1.
// k-contig operands use ldmatrix; i/j-contig use padded LDS.
// 256 threads, 8 warps in 2x4 (warp tile 64x32), block tile 128x128, BK=32.
#define BM 128
#define BN 128
#define BK 32
#define SKC 36   // smem row stride (words), k-contig layout [i][k]
#define SIC 136  // smem row stride (words), i-contig layout [k][i]
#define OPW 4608 // words per operand per stage = max(128*36, 32*136)

__device__ __forceinline__ void stage_tile(const float* __restrict__ src,
                                           long s0, long s1, int kc,
                                           uint32_t sbase, int t0, int kt, int tid) {
    if (kc) {  // k contiguous -> smem [i][k], stride SKC
#pragma unroll
        for (int it = 0; it < 4; it++) {
            int q = tid + it * 256;
            int row = q >> 3, kq = (q & 7) << 2;
            cp16(sbase + (uint32_t)(row * SKC + kq) * 4u,
                 src + (long)(t0 + row) * s0 + kt + kq);
        }
    } else {   // i contiguous -> smem [k][i], stride SIC
#pragma unroll
        for (int it = 0; it < 4; it++) {
            int q = tid + it * 256;
            int kr = q >> 5, iq = (q & 31) << 2;
            cp16(sbase + (uint32_t)(kr * SIC + iq) * 4u,
                 src + (long)(t0 + iq) + (long)(kt + kr) * s1);
        }
    }
}

__global__ void __launch_bounds__(256, 2)
tc_gemm_kernel(const float* __restrict__ A, long Ab, long As0, long As1,
               const float* __restrict__ Bp, long Bb, long Bs0, long Bs1,
               float* __restrict__ Cp, long Cb, long Cs0,
               const float* __restrict__ bias,
               const float* __restrict__ cbias,
               const float* __restrict__ addend, long Addb,
               float* rowsum, long Rsb,
               const float* __restrict__ colscale, long Csb,
               float scale, int accumulate, int Kd) {
    extern __shared__ uint32_t sm[];

    const int tid = threadIdx.x;
    const int wid = tid >> 5;
    const int lane = tid & 31;
    const int g = lane >> 2;
    const int t4 = lane & 3;
    const int wm = wid & 1;    // warp row (64 rows)
    const int wn = wid >> 1;   // warp col 0..3 (32 cols each)
    const int tr = lane & 7;   // ldmatrix row within 8
    const int tq = lane >> 3;  // ldmatrix quad (matrix select)

    const int aKc = (As1 == 1);
    const int bKc = (Bs1 == 1);

    const int bz = blockIdx.z;
    A += (size_t)bz * Ab;
    Bp += (size_t)bz * Bb;
    Cp += (size_t)bz * Cb;
    if (addend) addend += (size_t)bz * Addb;
    if (rowsum) rowsum += (size_t)bz * Rsb;
    if (colscale) colscale += (size_t)bz * Csb;

    const int i0 = blockIdx.y * BM;
    const int j0 = blockIdx.x * BN;

    const uint32_t smbase = smem_u32(sm);
    // ldmatrix per-thread base byte offsets within a tile
    // A quads: {rows +0, rows +8, cols +4 rows +0, cols +4 rows +8}
    const uint32_t aOff = (uint32_t)((wm * 64 + (tq & 1) * 8 + tr) * SKC + (tq >> 1) * 4) * 4u;
    // B quads: {nt rows, nt rows k+4, nt+1 rows, nt+1 rows k+4}
    const uint32_t bOff = (uint32_t)((wn * 32 + (tq >> 1) * 8 + tr) * SKC + (tq & 1) * 4) * 4u;

    float acc[4][4][4];
#pragma unroll
    for (int a = 0; a < 4; a++)
#pragma unroll
        for (int b = 0; b < 4; b++)
#pragma unroll
            for (int c = 0; c < 4; c++) acc[a][b][c] = 0.f;

    const int nch = Kd >> 5;

    stage_tile(A, As0, As1, aKc, smbase, i0, 0, tid);
    stage_tile(Bp, Bs0, Bs1, bKc, smbase + OPW * 4u, j0, 0, tid);
    asm volatile("cp.async.commit_group;" ::: "memory");

    for (int ch = 0; ch < nch; ch++) {
        if (ch + 1 < nch) {
            uint32_t sb = smbase + (uint32_t)(((ch + 1) & 1) * 2 * OPW) * 4u;
            stage_tile(A, As0, As1, aKc, sb, i0, (ch + 1) * BK, tid);
            stage_tile(Bp, Bs0, Bs1, bKc, sb + OPW * 4u, j0, (ch + 1) * BK, tid);
        }
        asm volatile("cp.async.commit_group;" ::: "memory");
        asm volatile("cp.async.wait_group 1;" ::: "memory");
        __syncthreads();

        const uint32_t* sA = sm + (ch & 1) * 2 * OPW;
        const uint32_t* sB = sA + OPW;
        const uint32_t sAu = smbase + (uint32_t)((ch & 1) * 2 * OPW) * 4u;
        const uint32_t sBu = sAu + OPW * 4u;

#pragma unroll
        for (int ks = 0; ks < BK; ks += 8) {
            uint32_t af[4][4];
            if (aKc) {
#pragma unroll
                for (int mt = 0; mt < 4; mt++)
                    ldsm_x4(af[mt][0], af[mt][1], af[mt][2], af[mt][3],
                            sAu + aOff + (uint32_t)(mt * 16 * SKC + ks) * 4u);
            } else {
#pragma unroll
                for (int mt = 0; mt < 4; mt++) {
                    int rb = wm * 64 + mt * 16 + g;
                    af[mt][0] = sA[(ks + t4    ) * SIC + rb    ];
                    af[mt][1] = sA[(ks + t4    ) * SIC + rb + 8];
                    af[mt][2] = sA[(ks + t4 + 4) * SIC + rb    ];
                    af[mt][3] = sA[(ks + t4 + 4) * SIC + rb + 8];
                }
            }
            uint32_t bf[4][2];
            if (bKc) {
#pragma unroll
                for (int p = 0; p < 2; p++)
                    ldsm_x4(bf[2 * p][0], bf[2 * p][1], bf[2 * p + 1][0], bf[2 * p + 1][1],
                            sBu + bOff + (uint32_t)(p * 16 * SKC + ks) * 4u);
            } else {
#pragma unroll
                for (int nt = 0; nt < 4; nt++) {
                    int cb = wn * 32 + nt * 8 + g;
                    bf[nt][0] = sB[(ks + t4    ) * SIC + cb];
                    bf[nt][1] = sB[(ks + t4 + 4) * SIC + cb];
                }
            }
#pragma unroll
            for (int mt = 0; mt < 4; mt++)
#pragma unroll
                for (int nt = 0; nt < 4; nt++)
                    mma_tf32(acc[mt][nt], af[mt], bf[nt]);
        }
        __syncthreads();
    }

    // ---- epilogue ----
    if (rowsum) {
#pragma unroll
        for (int mt = 0; mt < 4; mt++) {
#pragma unroll
            for (int half = 0; half < 2; half++) {
                int i = i0 + wm * 64 + mt * 16 + g + half * 8;
                float rs = 0.f;
#pragma unroll
                for (int nt = 0; nt < 4; nt++) {
                    int j = j0 + wn * 32 + nt * 8 + t4 * 2;
                    float e0 = __expf(acc[mt][nt][half * 2 + 0]);
                    float e1 = __expf(acc[mt][nt][half * 2 + 1]);
                    *(float2*)(Cp + (long)i * Cs0 + j) = make_float2(e0, e1);
                    rs += e0 + e1;
                }
                rs += __shfl_xor_sync(0xffffffffu, rs, 1);
                rs += __shfl_xor_sync(0xffffffffu, rs, 2);
                if (t4 == 0) atomicAdd(&rowsum[i], rs);
            }
        }
        return;
    }
#pragma unroll
    for (int mt = 0; mt < 4; mt++) {
#pragma unroll
        for (int half = 0; half < 2; half++) {
            int i = i0 + wm * 64 + mt * 16 + g + half * 8;
            float bi = bias ? scale * bias[i] : 0.f;
#pragma unroll
            for (int nt = 0; nt < 4; nt++) {
                int j = j0 + wn * 32 + nt * 8 + t4 * 2;
                long off = (long)i * Cs0 + j;
                float2 v;
                v.x = scale * acc[mt][nt][half * 2 + 0];
                v.y = scale * acc[mt][nt][half * 2 + 1];
                if (colscale) {
                    v.x *= colscale[j];
                    v.y *= colscale[j + 1];
                }
                v.x += bi; v.y += bi;
                if (cbias) {
                    v.x += scale * cbias[j];
                    v.y += scale * cbias[j + 1];
                }
                if (addend) {
                    float2 a2 = *(const float2*)(addend + off);
                    v.x += a2.x; v.y += a2.y;
                }
                if (accumulate) {
                    float2 o2 = *(const float2*)(Cp + off);
                    v.x += o2.x; v.y += o2.y;
                }
                *(float2*)(Cp + off) = v;
            }
        }
    }
}

// ---------------- bov = Wo @ bv (per attention) ----------------
__global__ void bov_kernel(const float* __restrict__ Wo,
                           const float* __restrict__ bv, int a) {
    int e = threadIdx.x;  // 256 threads
    const float* row = Wo + e * C_;
    float s = 0.f;
#pragma unroll 8
    for (int c = 0; c < C_; c++) s += row[c] * bv[c];
    g_bov[a * C_ + e] = s;
}

// ---------------- invert softmax denominators in place ----------------
__global__ void invden_kernel(int a) {
    int i = blockIdx.x * 256 + threadIdx.x;
    g_den[a * B_ * N_ + i] = 1.f / g_den[a * B_ * N_ + i];
}

// ---------------- mean over N per (b,c) ----------------
__global__ void mean_kernel(const float* __restrict__ x) {
    int bc = blockIdx.x;
    const float* row = x + (size_t)bc * N_;
    float s = 0.f;
    for (int n = threadIdx.x; n < N_; n += 256) s += row[n];
    __shared__ float sh[256];
    sh[threadIdx.x] = s;
    __syncthreads();
    for (int o = 128; o > 0; o >>= 1) {
        if (threadIdx.x < o) sh[threadIdx.x] += sh[threadIdx.x + o];
        __syncthreads();
    }
    if (threadIdx.x == 0) g_mean[bc] = sh[0] * (1.f / N_);
}

// ---------------- variation score per (b,n); also zeros denominators ------
__global__ void score_kernel(const float* __restrict__ x) {
    int b = blockIdx.y;
    int n = blockIdx.x * 256 + threadIdx.x;
    const float* xb = x + (size_t)b * C_ * N_;
    const float* mb = g_mean + b * C_;
    float acc = 0.f;
#pragma unroll 4
    for (int c = 0; c < C_; c++) {
        float v = xb[(size_t)c * N_ + n] - mb[c];
        acc += v * v;
    }
    int gi = b * N_ + n;
    g_score[gi] = acc;
    g_den[gi] = 0.f;
    g_den[B_ * N_ + gi] = 0.f;
}

// ---------------- per-batch bitonic full sort ----------------
__global__ void topk_kernel() {
    __shared__ float sk[N_];
    __shared__ int   sv[N_];
    int b = blockIdx.x;
    int t = threadIdx.x;
    for (int i = t; i < N_; i += 1024) {
        sk[i] = g_score[b * N_ + i];
        sv[i] = i;
    }
    __syncthreads();
    for (int k = 2; k <= N_; k <<= 1) {
        for (int j = k >> 1; j > 0; j >>= 1) {
            for (int i = t; i < N_; i += 1024) {
                int ixj = i ^ j;
                if (ixj > i) {
                    bool up = ((i & k) == 0);
                    float a = sk[i], c = sk[ixj];
                    bool sw = up ? (a > c) : (a < c);
                    if (sw) {
                        sk[i] = c; sk[ixj] = a;
                        int tv = sv[i]; sv[i] = sv[ixj]; sv[ixj] = tv;
                    }
                }
            }
            __syncthreads();
        }
    }
    if (t < M_) {
        g_idx[b * 2 * M_ + t]      = sv[N_ - 1 - t];  // sharp
        g_idx[b * 2 * M_ + M_ + t] = sv[t];           // gentle
    }
}

// ---------------- gather selected columns (both sets in one launch) -------
__global__ void gather_kernel(const float* __restrict__ x) {
    int m = blockIdx.x * 256 + threadIdx.x;
    int c = blockIdx.y;
    int b = blockIdx.z >> 1;
    int which = blockIdx.z & 1;
    const int* idx = g_idx + b * 2 * M_ + which * M_;
    float v = x[((size_t)b * C_ + c) * N_ + idx[m]];
    float* dst = which ? g_Xg : g_Xs;
    dst[((size_t)b * C_ + c) * M_ + m] = v;
}

// ---------------- per-channel batch stats ----------------
__global__ void chanstat_kernel() {
    int d = blockIdx.x;
    float s = 0.f, s2 = 0.f;
    for (int b = 0; b < B_; b++) {
        const float* row = g_Z + ((size_t)b * C_ + d) * N_;
        for (int n = threadIdx.x; n < N_; n += 256) {
            float v = row[n];
            s += v;
            s2 += v * v;
        }
    }
    __shared__ float shs[256];
    __shared__ float shq[256];
    shs[threadIdx.x] = s;
    shq[threadIdx.x] = s2;
    __syncthreads();
    for (int o = 128; o > 0; o >>= 1) {
        if (threadIdx.x < o) {
            shs[threadIdx.x] += shs[threadIdx.x + o];
            shq[threadIdx.x] += shq[threadIdx.x + o];
        }
        __syncthreads();
    }
    if (threadIdx.x == 0) {
        const float invBN = 1.f / (float)(B_ * N_);
        float mu = shs[0] * invBN;
        float var = shq[0] * invBN - mu * mu;
        g_mu[d] = mu;
        g_rstd[d] = rsqrtf(var + EPS_);
    }
}

// ---------------- BN + ReLU ----------------
__global__ void bnrelu_kernel(const float* __restrict__ gamma,
                              const float* __restrict__ beta,
                              float* __restrict__ out) {
    size_t i = (size_t)blockIdx.x * 256 + threadIdx.x;
    int d = (int)((i / N_) % C_);
    float v = (g_Z[i] - g_mu[d]) * g_rstd[d] * gamma[d] + beta[d];
    out[i] = fmaxf(v, 0.f);
}

// ---------------- host side ------------------------------------------------
static float* sym_f(const void* s) {
    void* p = nullptr;
    cudaGetSymbolAddress(&p, s);
    return (float*)p;
}

static constexpr int GEMM_SMEM = 4 * OPW * 4;  // 73728 bytes

static void launch_tc(const float* A, long Ab, long As0, long As1,
                      const float* Bp, long Bb, long Bs0, long Bs1,
                      float* Cp, long Cb, long Cs0,
                      const float* bias, const float* cbias,
                      const float* addend, long Addb,
                      float* rowsum, long Rsb,
                      const float* colscale, long Csb,
                      float scale, int accumulate, int Md, int Nd, int Kd,
                      int nbatch) {
    dim3 grid(Nd / BN, Md / BM, nbatch);
    tc_gemm_kernel<<<grid, 256, GEMM_SMEM>>>(
        A, Ab, As0, As1, Bp, Bb, Bs0, Bs1, Cp, Cb, Cs0,
        bias, cbias, addend, Addb, rowsum, Rsb, colscale, Csb,
        scale, accumulate, Kd);
}

extern "C" void kernel_launch(void* const* d_in, const int* in_sizes, int n_in,
                              void* d_out, int out_size) {
    static bool attr_done = false;
    if (!attr_done) {
        cudaFuncSetAttribute(tc_gemm_kernel,
                             cudaFuncAttributeMaxDynamicSharedMemorySize, GEMM_SMEM);
        attr_done = true;
    }

    const float* P[24];
    int p = 0;
    for (int i = 0; i < n_in && p < 24; i++) {
        if (in_sizes[i] == 1) continue;  // num_select scalar
        P[p++] = (const float*)d_in[i];
    }
    const float* x = P[0];
    const float* Wq[2] = {P[1], P[9]};
    const float* bq[2] = {P[2], P[10]};
    const float* Wk[2] = {P[3], P[11]};
    const float* bk[2] = {P[4], P[12]};
    const float* Wv[2] = {P[5], P[13]};
    const float* bv[2] = {P[6], P[14]};
    const float* Wo[2] = {P[7], P[15]};
    const float* bo[2] = {P[8], P[16]};
    const float* Wf = P[17];
    const float* bf = P[18];
    const float* gamma = P[19];
    const float* beta = P[20];
    float* out = (float*)d_out;

    float* Q   = sym_f(g_Q);
    float* K   = sym_f(g_K);
    float* WV  = sym_f(g_WV);
    float* S   = sym_f(g_S);
    float* Xs  = sym_f(g_Xs);
    float* Xg  = sym_f(g_Xg);
    float* ys  = sym_f(g_ys);
    float* yg  = sym_f(g_yg);
    float* Z   = sym_f(g_Z);
    float* den = sym_f(g_den);
    float* Wow = sym_f(g_Wow);
    float* bov = sym_f(g_bov);

    const long xB = (long)C_ * N_;
    const long cM = (long)C_ * M_;
    const long sB = (long)N_ * M_;

    // 1) geometry disentangle
    mean_kernel<<<B_ * C_, 256>>>(x);
    score_kernel<<<dim3(N_ / 256, B_), 256>>>(x);  // also zeros g_den
    topk_kernel<<<B_, 1024>>>();
    gather_kernel<<<dim3(M_ / 256, C_, 2 * B_), 256>>>(x);

    // 2) two cross-attentions
    for (int a = 0; a < 2; a++) {
        const float* Xctx = (a == 0) ? Xs : Xg;
        float* ybuf = (a == 0) ? ys : yg;
        float* dena = den + a * B_ * N_;
        float* Wowa = Wow + a * C_ * C_;
        float* bova = bov + a * C_;

        // Kt[m,d] = sum_c Xctx[c,m] Wk[d,c] + bk[d]  (i-contig A; B k-contig)
        launch_tc(Xctx, cM, 1, M_, Wk[a], 0, C_, 1, K, (long)M_ * C_, C_,
                  nullptr, bk[a], nullptr, 0, nullptr, 0, nullptr, 0,
                  1.f, 0, M_, C_, C_, B_);
        // Qt[n,d] = (sum_c x[c,n] Wq[d,c] + bq[d])/16
        launch_tc(x, xB, 1, N_, Wq[a], 0, C_, 1, Q, (long)N_ * C_, C_,
                  nullptr, bq[a], nullptr, 0, nullptr, 0, nullptr, 0,
                  0.0625f, 0, N_, C_, C_, B_);
        // Wow[e,c2] = sum_c Wo[e,c] Wv[c,c2]
        launch_tc(Wo[a], 0, C_, 1, Wv[a], 0, 1, C_, Wowa, 0, C_,
                  nullptr, nullptr, nullptr, 0, nullptr, 0, nullptr, 0,
                  1.f, 0, C_, C_, C_, 1);
        bov_kernel<<<1, 256>>>(Wo[a], bv[a], a);
        // E[n,m] = exp(sum_d Qt[n,d] Kt[m,d]); den += row sums  (both k-contig)
        launch_tc(Q, (long)N_ * C_, C_, 1, K, (long)M_ * C_, C_, 1, S, sB, M_,
                  nullptr, nullptr, nullptr, 0, dena, N_, nullptr, 0,
                  1.f, 0, N_, M_, C_, B_);
        invden_kernel<<<(B_ * N_) / 256, 256>>>(a);
        // WV[e,m] = Wow@Xctx + bov
        launch_tc(Wowa, 0, C_, 1, Xctx, cM, 1, M_, WV, cM, M_,
                  bova, nullptr, nullptr, 0, nullptr, 0, nullptr, 0,
                  1.f, 0, C_, M_, C_, B_);
        // y[e,n] = (sum_m WV[e,m] E[n,m]) * invden[b,n] + bo[e] + x[e,n]
        launch_tc(WV, cM, M_, 1, S, sB, M_, 1, ybuf, xB, N_,
                  bo[a], nullptr, x, xB, nullptr, 0, dena, N_,
                  1.f, 0, C_, N_, M_, B_);
    }

    // 3) fuse: Z = Wf[:, :C]@ys + Wf[:, C:]@yg + bf
    launch_tc(Wf, 0, 2 * C_, 1, ys, xB, 1, N_, Z, xB, N_,
              nullptr, nullptr, nullptr, 0, nullptr, 0, nullptr, 0,
              1.f, 0, C_, N_, C_, B_);
    launch_tc(Wf + C_, 0, 2 * C_, 1, yg, xB, 1, N_, Z, xB, N_,
              bf, nullptr, nullptr, 0, nullptr, 0, nullptr, 0,
              1.f, 1, C_, N_, C_, B_);

    // 4) batch-norm (training stats) + ReLU
    chanstat_kernel<<<C_, 256>>>();
    bnrelu_kernel<<<(B_ * C_ * N_) / 256, 256>>>(gamma, beta, out);
}

// round 10
// speedup vs baseline: 1.0898x; 1.0330x over previous
#include <cuda_runtime.h>
#include <cstdint>
#include <math.h>

// Problem dims (fixed by the reference)
static constexpr int B_ = 16;
static constexpr int C_ = 256;
static constexpr int N_ = 4096;
static constexpr int M_ = 1024;
static constexpr float EPS_ = 1e-5f;

// ---------------- scratch (static device globals; no allocation) ----------
__device__ float g_mean[B_ * C_];
__device__ float g_score[B_ * N_];
__device__ int   g_idx[B_ * 2 * M_];
__device__ float g_Xs[(size_t)B_ * C_ * M_];
__device__ float g_Xg[(size_t)B_ * C_ * M_];
__device__ float g_Q[(size_t)B_ * N_ * 2 * C_]; // Q^T both attns: [n][2C]
__device__ float g_K[(size_t)B_ * M_ * C_];     // K^T: [m][d], d contiguous
__device__ float g_WV[(size_t)B_ * C_ * M_];    // (Wo@Wv)@Xctx + Wo@bv
__device__ float g_S[(size_t)B_ * N_ * M_];     // E = exp(scores)
__device__ float g_y2[(size_t)B_ * 2 * C_ * N_];// [b][2C][n]: a*C block per attn
__device__ float g_Z[(size_t)B_ * C_ * N_];
__device__ float g_den[2 * B_ * N_];            // softmax denominators
__device__ float g_Wow[2 * C_ * C_];            // Wo @ Wv per attention
__device__ float g_bov[2 * C_];                 // Wo @ bv per attention
__device__ float g_Wq2[2 * C_ * C_];            // packed [Wq_s; Wq_g]
__device__ float g_bq2[2 * C_];                 // packed [bq_s; bq_g]
__device__ float g_cs[2 * C_];                  // channel sum / sumsq
__device__ float g_mu[C_];
__device__ float g_rstd[C_];

// ---------------- helpers --------------------------------------------------
// mma.tf32 reads the tf32 subset of the b32 register (truncation).
__device__ __forceinline__ void mma_tf32(float* c, const uint32_t* a, const uint32_t* b) {
    asm volatile(
        "mma.sync.aligned.m16n8k8.row.col.f32.tf32.tf32.f32 "
        "{%0,%1,%2,%3}, {%4,%5,%6,%7}, {%8,%9}, {%0,%1,%2,%3};"
        : "+f"(c[0]), "+f"(c[1]), "+f"(c[2]), "+f"(c[3])
        : "r"(a[0]), "r"(a[1]), "r"(a[2]), "r"(a[3]), "r"(b[0]), "r"(b[1]));
}
__device__ __forceinline__ void ldsm_x4(uint32_t& r0, uint32_t& r1,
                                        uint32_t& r2, uint32_t& r3, uint32_t addr) {
    asm volatile("ldmatrix.sync.aligned.m8n8.x4.shared.b16 {%0,%1,%2,%3}, [%4];"
                 : "=r"(r0), "=r"(r1), "=r"(r2), "=r"(r3) : "r"(addr));
}
__device__ __forceinline__ uint32_t smem_u32(const void* p) {
    uint32_t a;
    asm("{ .reg .u64 t; cvta.to.shared.u64 t, %1; cvt.u32.u64 %0, t; }"
        : "=r"(a) : "l"(p));
    return a;
}
__device__ __forceinline__ void cp16(uint32_t saddr, const float* g) {
    asm volatile("cp.async.cg.shared.global [%0], [%1], 16;" :: "r"(saddr), "l"(g));
}

// ================== pipelined warp-MMA tf32 generic strided GEMM ==========
// Normal: D[i,j] = scale*acc [*colscale[j]] + scale*(bias[i]+cbias[j])
//                  [+addend] ; if chansum: atomic per-channel sum/sumsq of D
// Exp mode (rowsum != nullptr):
//   D[i,j] = exp(acc[i,j]); rowsum[i] += sum_j D[i,j] (atomic)
// A(i,k) = A[i*As0 + k*As1]; B(j,k) = B[j*Bs0 + k*Bs1]; one stride is 1.
// k-contig operands use ldmatrix; i/j-contig use padded LDS.
// 256 threads, 8 warps in 2x4 (warp tile 64x32), block tile 128x128, BK=32.
#define BM 128
#define BN 128
#define BK 32
#define SKC 36   // smem row stride (words), k-contig layout [i][k]
#define SIC 136  // smem row stride (words), i-contig layout [k][i]
#define OPW 4608 // words per operand per stage = max(128*36, 32*136)

__device__ __forceinline__ void stage_tile(const float* __restrict__ src,
                                           long s0, long s1, int kc,
                                           uint32_t sbase, int t0, int kt, int tid) {
    if (kc) {  // k contiguous -> smem [i][k], stride SKC
#pragma unroll
        for (int it = 0; it < 4; it++) {
            int q = tid + it * 256;
            int row = q >> 3, kq = (q & 7) << 2;
            cp16(sbase + (uint32_t)(row * SKC + kq) * 4u,
                 src + (long)(t0 + row) * s0 + kt + kq);
        }
    } else {   // i contiguous -> smem [k][i], stride SIC
#pragma unroll
        for (int it = 0; it < 4; it++) {
            int q = tid + it * 256;
            int kr = q >> 5, iq = (q & 31) << 2;
            cp16(sbase + (uint32_t)(kr * SIC + iq) * 4u,
                 src + (long)(t0 + iq) + (long)(kt + kr) * s1);
        }
    }
}

__global__ void __launch_bounds__(256, 2)
tc_gemm_kernel(const float* __restrict__ A, long Ab, long As0, long As1,
               const float* __restrict__ Bp, long Bb, long Bs0, long Bs1,
               float* __restrict__ Cp, long Cb, long Cs0,
               const float* __restrict__ bias,
               const float* __restrict__ cbias,
               const float* __restrict__ addend, long Addb,
               float* rowsum, long Rsb,
               const float* __restrict__ colscale, long Csb,
               float* chansum,
               float scale, int Kd) {
    extern __shared__ uint32_t sm[];

    const int tid = threadIdx.x;
    const int wid = tid >> 5;
    const int lane = tid & 31;
    const int g = lane >> 2;
    const int t4 = lane & 3;
    const int wm = wid & 1;    // warp row (64 rows)
    const int wn = wid >> 1;   // warp col 0..3 (32 cols each)
    const int tr = lane & 7;   // ldmatrix row within 8
    const int tq = lane >> 3;  // ldmatrix quad (matrix select)

    const int aKc = (As1 == 1);
    const int bKc = (Bs1 == 1);

    const int bz = blockIdx.z;
    A += (size_t)bz * Ab;
    Bp += (size_t)bz * Bb;
    Cp += (size_t)bz * Cb;
    if (addend) addend += (size_t)bz * Addb;
    if (rowsum) rowsum += (size_t)bz * Rsb;
    if (colscale) colscale += (size_t)bz * Csb;

    const int i0 = blockIdx.y * BM;
    const int j0 = blockIdx.x * BN;

    const uint32_t smbase = smem_u32(sm);
    const uint32_t aOff = (uint32_t)((wm * 64 + (tq & 1) * 8 + tr) * SKC + (tq >> 1) * 4) * 4u;
    const uint32_t bOff = (uint32_t)((wn * 32 + (tq >> 1) * 8 + tr) * SKC + (tq & 1) * 4) * 4u;

    float acc[4][4][4];
#pragma unroll
    for (int a = 0; a < 4; a++)
#pragma unroll
        for (int b = 0; b < 4; b++)
#pragma unroll
            for (int c = 0; c < 4; c++) acc[a][b][c] = 0.f;

    const int nch = Kd >> 5;

    stage_tile(A, As0, As1, aKc, smbase, i0, 0, tid);
    stage_tile(Bp, Bs0, Bs1, bKc, smbase + OPW * 4u, j0, 0, tid);
    asm volatile("cp.async.commit_group;" ::: "memory");

    for (int ch = 0; ch < nch; ch++) {
        if (ch + 1 < nch) {
            uint32_t sb = smbase + (uint32_t)(((ch + 1) & 1) * 2 * OPW) * 4u;
            stage_tile(A, As0, As1, aKc, sb, i0, (ch + 1) * BK, tid);
            stage_tile(Bp, Bs0, Bs1, bKc, sb + OPW * 4u, j0, (ch + 1) * BK, tid);
        }
        asm volatile("cp.async.commit_group;" ::: "memory");
        asm volatile("cp.async.wait_group 1;" ::: "memory");
        __syncthreads();

        const uint32_t* sA = sm + (ch & 1) * 2 * OPW;
        const uint32_t* sB = sA + OPW;
        const uint32_t sAu = smbase + (uint32_t)((ch & 1) * 2 * OPW) * 4u;
        const uint32_t sBu = sAu + OPW * 4u;

#pragma unroll
        for (int ks = 0; ks < BK; ks += 8) {
            uint32_t af[4][4];
            if (aKc) {
#pragma unroll
                for (int mt = 0; mt < 4; mt++)
                    ldsm_x4(af[mt][0], af[mt][1], af[mt][2], af[mt][3],
                            sAu + aOff + (uint32_t)(mt * 16 * SKC + ks) * 4u);
            } else {
#pragma unroll
                for (int mt = 0; mt < 4; mt++) {
                    int rb = wm * 64 + mt * 16 + g;
                    af[mt][0] = sA[(ks + t4    ) * SIC + rb    ];
                    af[mt][1] = sA[(ks + t4    ) * SIC + rb + 8];
                    af[mt][2] = sA[(ks + t4 + 4) * SIC + rb    ];
                    af[mt][3] = sA[(ks + t4 + 4) * SIC + rb + 8];
                }
            }
            uint32_t bf[4][2];
            if (bKc) {
#pragma unroll
                for (int p = 0; p < 2; p++)
                    ldsm_x4(bf[2 * p][0], bf[2 * p][1], bf[2 * p + 1][0], bf[2 * p + 1][1],
                            sBu + bOff + (uint32_t)(p * 16 * SKC + ks) * 4u);
            } else {
#pragma unroll
                for (int nt = 0; nt < 4; nt++) {
                    int cb = wn * 32 + nt * 8 + g;
                    bf[nt][0] = sB[(ks + t4    ) * SIC + cb];
                    bf[nt][1] = sB[(ks + t4 + 4) * SIC + cb];
                }
            }
#pragma unroll
            for (int mt = 0; mt < 4; mt++)
#pragma unroll
                for (int nt = 0; nt < 4; nt++)
                    mma_tf32(acc[mt][nt], af[mt], bf[nt]);
        }
        __syncthreads();
    }

    // ---- epilogue ----
    if (rowsum) {
#pragma unroll
        for (int mt = 0; mt < 4; mt++) {
#pragma unroll
            for (int half = 0; half < 2; half++) {
                int i = i0 + wm * 64 + mt * 16 + g + half * 8;
                float rs = 0.f;
#pragma unroll
                for (int nt = 0; nt < 4; nt++) {
                    int j = j0 + wn * 32 + nt * 8 + t4 * 2;
                    float e0 = __expf(acc[mt][nt][half * 2 + 0]);
                    float e1 = __expf(acc[mt][nt][half * 2 + 1]);
                    *(float2*)(Cp + (long)i * Cs0 + j) = make_float2(e0, e1);
                    rs += e0 + e1;
                }
                rs += __shfl_xor_sync(0xffffffffu, rs, 1);
                rs += __shfl_xor_sync(0xffffffffu, rs, 2);
                if (t4 == 0) atomicAdd(&rowsum[i], rs);
            }
        }
        return;
    }
#pragma unroll
    for (int mt = 0; mt < 4; mt++) {
#pragma unroll
        for (int half = 0; half < 2; half++) {
            int i = i0 + wm * 64 + mt * 16 + g + half * 8;
            float bi = bias ? scale * bias[i] : 0.f;
            float rs = 0.f, rq = 0.f;
#pragma unroll
            for (int nt = 0; nt < 4; nt++) {
                int j = j0 + wn * 32 + nt * 8 + t4 * 2;
                long off = (long)i * Cs0 + j;
                float2 v;
                v.x = scale * acc[mt][nt][half * 2 + 0];
                v.y = scale * acc[mt][nt][half * 2 + 1];
                if (colscale) {
                    v.x *= colscale[j];
                    v.y *= colscale[j + 1];
                }
                v.x += bi; v.y += bi;
                if (cbias) {
                    v.x += scale * cbias[j];
                    v.y += scale * cbias[j + 1];
                }
                if (addend) {
                    float2 a2 = *(const float2*)(addend + off);
                    v.x += a2.x; v.y += a2.y;
                }
                *(float2*)(Cp + off) = v;
                if (chansum) {
                    rs += v.x + v.y;
                    rq += v.x * v.x + v.y * v.y;
                }
            }
            if (chansum) {
                rs += __shfl_xor_sync(0xffffffffu, rs, 1);
                rs += __shfl_xor_sync(0xffffffffu, rs, 2);
                rq += __shfl_xor_sync(0xffffffffu, rq, 1);
                rq += __shfl_xor_sync(0xffffffffu, rq, 2);
                if (t4 == 0) {
                    atomicAdd(&chansum[i], rs);
                    atomicAdd(&chansum[C_ + i], rq);
                }
            }
        }
    }
}

// ---------------- pack [Wq_s; Wq_g] and biases ----------------
__global__ void packq_kernel(const float* __restrict__ Wqs,
                             const float* __restrict__ bqs,
                             const float* __restrict__ Wqg,
                             const float* __restrict__ bqg) {
    int r = blockIdx.x;  // 0..511
    int c = threadIdx.x;
    g_Wq2[r * C_ + c] = (r < C_) ? Wqs[r * C_ + c] : Wqg[(r - C_) * C_ + c];
    if (c == 0) g_bq2[r] = (r < C_) ? bqs[r] : bqg[r - C_];
}

// ---------------- bov = Wo @ bv (per attention) ----------------
__global__ void bov_kernel(const float* __restrict__ Wo,
                           const float* __restrict__ bv, int a) {
    int e = threadIdx.x;  // 256 threads
    const float* row = Wo + e * C_;
    float s = 0.f;
#pragma unroll 8
    for (int c = 0; c < C_; c++) s += row[c] * bv[c];
    g_bov[a * C_ + e] = s;
}

// ---------------- invert softmax denominators in place ----------------
__global__ void invden_kernel(int a) {
    int i = blockIdx.x * 256 + threadIdx.x;
    g_den[a * B_ * N_ + i] = 1.f / g_den[a * B_ * N_ + i];
}

// ---------------- finalize channel stats ----------------
__global__ void statfin_kernel() {
    int d = threadIdx.x;
    const float invBN = 1.f / (float)(B_ * N_);
    float mu = g_cs[d] * invBN;
    float var = g_cs[C_ + d] * invBN - mu * mu;
    g_mu[d] = mu;
    g_rstd[d] = rsqrtf(var + EPS_);
}

// ---------------- mean over N per (b,c) ----------------
__global__ void mean_kernel(const float* __restrict__ x) {
    int bc = blockIdx.x;
    const float* row = x + (size_t)bc * N_;
    float s = 0.f;
    for (int n = threadIdx.x; n < N_; n += 256) s += row[n];
    __shared__ float sh[256];
    sh[threadIdx.x] = s;
    __syncthreads();
    for (int o = 128; o > 0; o >>= 1) {
        if (threadIdx.x < o) sh[threadIdx.x] += sh[threadIdx.x + o];
        __syncthreads();
    }
    if (threadIdx.x == 0) g_mean[bc] = sh[0] * (1.f / N_);
}

// ------- variation score per (b,n); zeros denominators + stat accum -------
__global__ void score_kernel(const float* __restrict__ x) {
    int b = blockIdx.y;
    int n = blockIdx.x * 256 + threadIdx.x;
    const float* xb = x + (size_t)b * C_ * N_;
    const float* mb = g_mean + b * C_;
    float acc = 0.f;
#pragma unroll 4
    for (int c = 0; c < C_; c++) {
        float v = xb[(size_t)c * N_ + n] - mb[c];
        acc += v * v;
    }
    int gi = b * N_ + n;
    g_score[gi] = acc;
    g_den[gi] = 0.f;
    g_den[B_ * N_ + gi] = 0.f;
    if (gi < 2 * C_) g_cs[gi] = 0.f;
}

// ---------------- per-batch bitonic full sort ----------------
__global__ void topk_kernel() {
    __shared__ float sk[N_];
    __shared__ int   sv[N_];
    int b = blockIdx.x;
    int t = threadIdx.x;
    for (int i = t; i < N_; i += 1024) {
        sk[i] = g_score[b * N_ + i];
        sv[i] = i;
    }
    __syncthreads();
    for (int k = 2; k <= N_; k <<= 1) {
        for (int j = k >> 1; j > 0; j >>= 1) {
            for (int i = t; i < N_; i += 1024) {
                int ixj = i ^ j;
                if (ixj > i) {
                    bool up = ((i & k) == 0);
                    float a = sk[i], c = sk[ixj];
                    bool sw = up ? (a > c) : (a < c);
                    if (sw) {
                        sk[i] = c; sk[ixj] = a;
                        int tv = sv[i]; sv[i] = sv[ixj]; sv[ixj] = tv;
                    }
                }
            }
            __syncthreads();
        }
    }
    if (t < M_) {
        g_idx[b * 2 * M_ + t]      = sv[N_ - 1 - t];  // sharp
        g_idx[b * 2 * M_ + M_ + t] = sv[t];           // gentle
    }
}

// ---------------- gather selected columns (both sets in one launch) -------
__global__ void gather_kernel(const float* __restrict__ x) {
    int m = blockIdx.x * 256 + threadIdx.x;
    int c = blockIdx.y;
    int b = blockIdx.z >> 1;
    int which = blockIdx.z & 1;
    const int* idx = g_idx + b * 2 * M_ + which * M_;
    float v = x[((size_t)b * C_ + c) * N_ + idx[m]];
    float* dst = which ? g_Xg : g_Xs;
    dst[((size_t)b * C_ + c) * M_ + m] = v;
}

// ---------------- BN + ReLU ----------------
__global__ void bnrelu_kernel(const float* __restrict__ gamma,
                              const float* __restrict__ beta,
                              float* __restrict__ out) {
    size_t i = (size_t)blockIdx.x * 256 + threadIdx.x;
    int d = (int)((i / N_) % C_);
    float v = (g_Z[i] - g_mu[d]) * g_rstd[d] * gamma[d] + beta[d];
    out[i] = fmaxf(v, 0.f);
}

// ---------------- host side ------------------------------------------------
static float* sym_f(const void* s) {
    void* p = nullptr;
    cudaGetSymbolAddress(&p, s);
    return (float*)p;
}

static constexpr int GEMM_SMEM = 4 * OPW * 4;  // 73728 bytes

static void launch_tc(const float* A, long Ab, long As0, long As1,
                      const float* Bp, long Bb, long Bs0, long Bs1,
                      float* Cp, long Cb, long Cs0,
                      const float* bias, const float* cbias,
                      const float* addend, long Addb,
                      float* rowsum, long Rsb,
                      const float* colscale, long Csb,
                      float* chansum,
                      float scale, int Md, int Nd, int Kd, int nbatch) {
    dim3 grid(Nd / BN, Md / BM, nbatch);
    tc_gemm_kernel<<<grid, 256, GEMM_SMEM>>>(
        A, Ab, As0, As1, Bp, Bb, Bs0, Bs1, Cp, Cb, Cs0,
        bias, cbias, addend, Addb, rowsum, Rsb, colscale, Csb, chansum,
        scale, Kd);
}

extern "C" void kernel_launch(void* const* d_in, const int* in_sizes, int n_in,
                              void* d_out, int out_size) {
    static bool attr_done = false;
    if (!attr_done) {
        cudaFuncSetAttribute(tc_gemm_kernel,
                             cudaFuncAttributeMaxDynamicSharedMemorySize, GEMM_SMEM);
        attr_done = true;
    }

    const float* P[24];
    int p = 0;
    for (int i = 0; i < n_in && p < 24; i++) {
        if (in_sizes[i] == 1) continue;  // num_select scalar
        P[p++] = (const float*)d_in[i];
    }
    const float* x = P[0];
    const float* Wq[2] = {P[1], P[9]};
    const float* bq[2] = {P[2], P[10]};
    const float* Wk[2] = {P[3], P[11]};
    const float* bk[2] = {P[4], P[12]};
    const float* Wv[2] = {P[5], P[13]};
    const float* bv[2] = {P[6], P[14]};
    const float* Wo[2] = {P[7], P[15]};
    const float* bo[2] = {P[8], P[16]};
    const float* Wf = P[17];
    const float* bf = P[18];
    const float* gamma = P[19];
    const float* beta = P[20];
    float* out = (float*)d_out;

    float* Q   = sym_f(g_Q);
    float* K   = sym_f(g_K);
    float* WV  = sym_f(g_WV);
    float* S   = sym_f(g_S);
    float* Xs  = sym_f(g_Xs);
    float* Xg  = sym_f(g_Xg);
    float* y2  = sym_f(g_y2);
    float* Z   = sym_f(g_Z);
    float* den = sym_f(g_den);
    float* Wow = sym_f(g_Wow);
    float* bov = sym_f(g_bov);
    float* Wq2 = sym_f(g_Wq2);
    float* bq2 = sym_f(g_bq2);
    float* cs  = sym_f(g_cs);

    const long xB = (long)C_ * N_;
    const long cM = (long)C_ * M_;
    const long sB = (long)N_ * M_;
    const long qB = (long)N_ * 2 * C_;
    const long yB = (long)2 * C_ * N_;

    // 1) geometry disentangle
    mean_kernel<<<B_ * C_, 256>>>(x);
    score_kernel<<<dim3(N_ / 256, B_), 256>>>(x);  // zeros g_den + g_cs
    topk_kernel<<<B_, 1024>>>();
    gather_kernel<<<dim3(M_ / 256, C_, 2 * B_), 256>>>(x);

    // 2) merged Q projection for both attentions:
    //    Q[b][n][d2] = (sum_c x[c,n] Wq2[d2,c] + bq2[d2]) / 16,  d2 in [0,512)
    packq_kernel<<<2 * C_, 256>>>(Wq[0], bq[0], Wq[1], bq[1]);
    launch_tc(x, xB, 1, N_, Wq2, 0, C_, 1, Q, qB, 2 * C_,
              nullptr, bq2, nullptr, 0, nullptr, 0, nullptr, 0, nullptr,
              0.0625f, N_, 2 * C_, C_, B_);

    // 3) two cross-attentions
    for (int a = 0; a < 2; a++) {
        const float* Xctx = (a == 0) ? Xs : Xg;
        float* ybuf = y2 + (size_t)a * C_ * N_;
        float* dena = den + a * B_ * N_;
        float* Wowa = Wow + a * C_ * C_;
        float* bova = bov + a * C_;

        // Kt[m,d] = sum_c Xctx[c,m] Wk[d,c] + bk[d]
        launch_tc(Xctx, cM, 1, M_, Wk[a], 0, C_, 1, K, (long)M_ * C_, C_,
                  nullptr, bk[a], nullptr, 0, nullptr, 0, nullptr, 0, nullptr,
                  1.f, M_, C_, C_, B_);
        // Wow[e,c2] = sum_c Wo[e,c] Wv[c,c2]
        launch_tc(Wo[a], 0, C_, 1, Wv[a], 0, 1, C_, Wowa, 0, C_,
                  nullptr, nullptr, nullptr, 0, nullptr, 0, nullptr, 0, nullptr,
                  1.f, C_, C_, C_, 1);
        bov_kernel<<<1, 256>>>(Wo[a], bv[a], a);
        // E[n,m] = exp(sum_d Q[n, a*256+d] Kt[m,d]); den += row sums
        launch_tc(Q + a * C_, qB, 2 * C_, 1, K, (long)M_ * C_, C_, 1, S, sB, M_,
                  nullptr, nullptr, nullptr, 0, dena, N_, nullptr, 0, nullptr,
                  1.f, N_, M_, C_, B_);
        invden_kernel<<<(B_ * N_) / 256, 256>>>(a);
        // WV[e,m] = Wow@Xctx + bov
        launch_tc(Wowa, 0, C_, 1, Xctx, cM, 1, M_, WV, cM, M_,
                  bova, nullptr, nullptr, 0, nullptr, 0, nullptr, 0, nullptr,
                  1.f, C_, M_, C_, B_);
        // y2[b][a*C+e][n] = (sum_m WV[e,m] E[n,m]) * invden[b,n] + bo[e] + x[e,n]
        launch_tc(WV, cM, M_, 1, S, sB, M_, 1, ybuf, yB, N_,
                  bo[a], nullptr, x, xB, nullptr, 0, dena, N_, nullptr,
                  1.f, C_, N_, M_, B_);
    }

    // 4) fuse (single GEMM, K=512): Z = Wf @ y2 + bf; stats in epilogue
    launch_tc(Wf, 0, 2 * C_, 1, y2, yB, 1, N_, Z, xB, N_,
              bf, nullptr, nullptr, 0, nullptr, 0, nullptr, 0, cs,
              1.f, C_, N_, 2 * C_, B_);

    // 5) batch-norm (training stats) + ReLU
    statfin_kernel<<<1, 256>>>();
    bnrelu_kernel<<<(B_ * C_ * N_) / 256, 256>>>(gamma, beta, out);
}

// round 11
// speedup vs baseline: 1.1023x; 1.0115x over previous
#include <cuda_runtime.h>
#include <cstdint>
#include <math.h>

// Problem dims (fixed by the reference)
static constexpr int B_ = 16;
static constexpr int C_ = 256;
static constexpr int N_ = 4096;
static constexpr int M_ = 1024;
static constexpr float EPS_ = 1e-5f;

// ---------------- scratch (static device globals; no allocation) ----------
__device__ float g_mean[B_ * C_];
__device__ float g_score[B_ * N_];
__device__ int   g_idx[B_ * 2 * M_];
__device__ float g_Xs[(size_t)B_ * C_ * M_];
__device__ float g_Xg[(size_t)B_ * C_ * M_];
__device__ float g_Q[(size_t)B_ * N_ * 2 * C_]; // Q^T both attns: [n][2C]
__device__ float g_K[(size_t)B_ * M_ * C_];     // K^T: [m][d], d contiguous
__device__ float g_WV[(size_t)B_ * C_ * M_];    // (Wo@Wv)@Xctx + Wo@bv
__device__ float g_S[(size_t)B_ * N_ * M_];     // E = exp(scores)
__device__ float g_y2[(size_t)B_ * 2 * C_ * N_];// [b][2C][n]: a*C block per attn
__device__ float g_Z[(size_t)B_ * C_ * N_];
__device__ float g_den[2 * B_ * N_];            // softmax denominators
__device__ float g_Wow[2 * C_ * C_];            // Wo @ Wv per attention
__device__ float g_bov[2 * C_];                 // Wo @ bv per attention
__device__ float g_Wq2[2 * C_ * C_];            // packed [Wq_s; Wq_g]
__device__ float g_bq2[2 * C_];                 // packed [bq_s; bq_g]
__device__ float g_cs[2 * C_];                  // channel sum / sumsq
__device__ float g_mu[C_];
__device__ float g_rstd[C_];

// ---------------- helpers --------------------------------------------------
// mma.tf32 reads the tf32 subset of the b32 register (truncation).
__device__ __forceinline__ void mma_tf32(float* c, const uint32_t* a, const uint32_t* b) {
    asm volatile(
        "mma.sync.aligned.m16n8k8.row.col.f32.tf32.tf32.f32 "
        "{%0,%1,%2,%3}, {%4,%5,%6,%7}, {%8,%9}, {%0,%1,%2,%3};"
        : "+f"(c[0]), "+f"(c[1]), "+f"(c[2]), "+f"(c[3])
        : "r"(a[0]), "r"(a[1]), "r"(a[2]), "r"(a[3]), "r"(b[0]), "r"(b[1]));
}
__device__ __forceinline__ void ldsm_x4(uint32_t& r0, uint32_t& r1,
                                        uint32_t& r2, uint32_t& r3, uint32_t addr) {
    asm volatile("ldmatrix.sync.aligned.m8n8.x4.shared.b16 {%0,%1,%2,%3}, [%4];"
                 : "=r"(r0), "=r"(r1), "=r"(r2), "=r"(r3) : "r"(addr));
}
__device__ __forceinline__ uint32_t smem_u32(const void* p) {
    uint32_t a;
    asm("{ .reg .u64 t; cvta.to.shared.u64 t, %1; cvt.u32.u64 %0, t; }"
        : "=r"(a) : "l"(p));
    return a;
}
__device__ __forceinline__ void cp16(uint32_t saddr, const float* g) {
    asm volatile("cp.async.cg.shared.global [%0], [%1], 16;" :: "r"(saddr), "l"(g));
}

// ================== pipelined warp-MMA tf32 generic strided GEMM ==========
// Normal: D[i,j] = scale*acc [*colscale[j]] + scale*(bias[i]+cbias[j])
//                  [+addend] ; if chansum: atomic per-channel sum/sumsq of D
// Exp mode (rowsum != nullptr):
//   D[i,j] = exp(acc[i,j]); rowsum[i] += sum_j D[i,j] (atomic)
// A(i,k) = A[i*As0 + k*As1]; B(j,k) = B[j*Bs0 + k*Bs1]; one stride is 1.
// k-contig operands use ldmatrix; i/j-contig use padded LDS.
// 256 threads, 8 warps in 2x4 (warp tile 64x32), block tile 128x128, BK=32.
// 3-stage cp.async pipeline, ONE __syncthreads per chunk.
#define BM 128
#define BN 128
#define BK 32
#define NSTAGE 3
#define SKC 36   // smem row stride (words), k-contig layout [i][k]
#define SIC 136  // smem row stride (words), i-contig layout [k][i]
#define OPW 4608 // words per operand per stage = max(128*36, 32*136)

__device__ __forceinline__ void stage_tile(const float* __restrict__ src,
                                           long s0, long s1, int kc,
                                           uint32_t sbase, int t0, int kt, int tid) {
    if (kc) {  // k contiguous -> smem [i][k], stride SKC
#pragma unroll
        for (int it = 0; it < 4; it++) {
            int q = tid + it * 256;
            int row = q >> 3, kq = (q & 7) << 2;
            cp16(sbase + (uint32_t)(row * SKC + kq) * 4u,
                 src + (long)(t0 + row) * s0 + kt + kq);
        }
    } else {   // i contiguous -> smem [k][i], stride SIC
#pragma unroll
        for (int it = 0; it < 4; it++) {
            int q = tid + it * 256;
            int kr = q >> 5, iq = (q & 31) << 2;
            cp16(sbase + (uint32_t)(kr * SIC + iq) * 4u,
                 src + (long)(t0 + iq) + (long)(kt + kr) * s1);
        }
    }
}

__global__ void __launch_bounds__(256, 2)
tc_gemm_kernel(const float* __restrict__ A, long Ab, long As0, long As1,
               const float* __restrict__ Bp, long Bb, long Bs0, long Bs1,
               float* __restrict__ Cp, long Cb, long Cs0,
               const float* __restrict__ bias,
               const float* __restrict__ cbias,
               const float* __restrict__ addend, long Addb,
               float* rowsum, long Rsb,
               const float* __restrict__ colscale, long Csb,
               float* chansum,
               float scale, int Kd) {
    extern __shared__ uint32_t sm[];

    const int tid = threadIdx.x;
    const int wid = tid >> 5;
    const int lane = tid & 31;
    const int g = lane >> 2;
    const int t4 = lane & 3;
    const int wm = wid & 1;    // warp row (64 rows)
    const int wn = wid >> 1;   // warp col 0..3 (32 cols each)
    const int tr = lane & 7;   // ldmatrix row within 8
    const int tq = lane >> 3;  // ldmatrix quad (matrix select)

    const int aKc = (As1 == 1);
    const int bKc = (Bs1 == 1);

    const int bz = blockIdx.z;
    A += (size_t)bz * Ab;
    Bp += (size_t)bz * Bb;
    Cp += (size_t)bz * Cb;
    if (addend) addend += (size_t)bz * Addb;
    if (rowsum) rowsum += (size_t)bz * Rsb;
    if (colscale) colscale += (size_t)bz * Csb;

    const int i0 = blockIdx.y * BM;
    const int j0 = blockIdx.x * BN;

    const uint32_t smbase = smem_u32(sm);
    const uint32_t aOff = (uint32_t)((wm * 64 + (tq & 1) * 8 + tr) * SKC + (tq >> 1) * 4) * 4u;
    const uint32_t bOff = (uint32_t)((wn * 32 + (tq >> 1) * 8 + tr) * SKC + (tq & 1) * 4) * 4u;

    float acc[4][4][4];
#pragma unroll
    for (int a = 0; a < 4; a++)
#pragma unroll
        for (int b = 0; b < 4; b++)
#pragma unroll
            for (int c = 0; c < 4; c++) acc[a][b][c] = 0.f;

    const int nch = Kd >> 5;

    // prologue: stage chunks 0 and 1 into stages 0 and 1
    stage_tile(A, As0, As1, aKc, smbase, i0, 0, tid);
    stage_tile(Bp, Bs0, Bs1, bKc, smbase + OPW * 4u, j0, 0, tid);
    asm volatile("cp.async.commit_group;" ::: "memory");
    if (nch > 1) {
        uint32_t sb1 = smbase + (uint32_t)(2 * OPW) * 4u;
        stage_tile(A, As0, As1, aKc, sb1, i0, BK, tid);
        stage_tile(Bp, Bs0, Bs1, bKc, sb1 + OPW * 4u, j0, BK, tid);
    }
    asm volatile("cp.async.commit_group;" ::: "memory");

    int st = 0;      // stage index of current chunk
    int stw = 2;     // stage index for prefetch (ch+2)
    for (int ch = 0; ch < nch; ch++) {
        asm volatile("cp.async.wait_group 1;" ::: "memory");
        __syncthreads();

        const uint32_t* sA = sm + st * 2 * OPW;
        const uint32_t* sB = sA + OPW;
        const uint32_t sAu = smbase + (uint32_t)(st * 2 * OPW) * 4u;
        const uint32_t sBu = sAu + OPW * 4u;

#pragma unroll
        for (int ks = 0; ks < BK; ks += 8) {
            uint32_t af[4][4];
            if (aKc) {
#pragma unroll
                for (int mt = 0; mt < 4; mt++)
                    ldsm_x4(af[mt][0], af[mt][1], af[mt][2], af[mt][3],
                            sAu + aOff + (uint32_t)(mt * 16 * SKC + ks) * 4u);
            } else {
#pragma unroll
                for (int mt = 0; mt < 4; mt++) {
                    int rb = wm * 64 + mt * 16 + g;
                    af[mt][0] = sA[(ks + t4    ) * SIC + rb    ];
                    af[mt][1] = sA[(ks + t4    ) * SIC + rb + 8];
                    af[mt][2] = sA[(ks + t4 + 4) * SIC + rb    ];
                    af[mt][3] = sA[(ks + t4 + 4) * SIC + rb + 8];
                }
            }
            uint32_t bf[4][2];
            if (bKc) {
#pragma unroll
                for (int p = 0; p < 2; p++)
                    ldsm_x4(bf[2 * p][0], bf[2 * p][1], bf[2 * p + 1][0], bf[2 * p + 1][1],
                            sBu + bOff + (uint32_t)(p * 16 * SKC + ks) * 4u);
            } else {
#pragma unroll
                for (int nt = 0; nt < 4; nt++) {
                    int cb = wn * 32 + nt * 8 + g;
                    bf[nt][0] = sB[(ks + t4    ) * SIC + cb];
                    bf[nt][1] = sB[(ks + t4 + 4) * SIC + cb];
                }
            }
#pragma unroll
            for (int mt = 0; mt < 4; mt++)
#pragma unroll
                for (int nt = 0; nt < 4; nt++)
                    mma_tf32(acc[mt][nt], af[mt], bf[nt]);
        }

        // prefetch chunk ch+2 (safe: distinct stage; all warps passed the
        // top sync, so compute(ch-1) on this stage's buffer is complete)
        if (ch + 2 < nch) {
            uint32_t sb = smbase + (uint32_t)(stw * 2 * OPW) * 4u;
            stage_tile(A, As0, As1, aKc, sb, i0, (ch + 2) * BK, tid);
            stage_tile(Bp, Bs0, Bs1, bKc, sb + OPW * 4u, j0, (ch + 2) * BK, tid);
        }
        asm volatile("cp.async.commit_group;" ::: "memory");

        if (++st == NSTAGE) st = 0;
        if (++stw == NSTAGE) stw = 0;
    }

    // ---- epilogue ----
    if (rowsum) {
#pragma unroll
        for (int mt = 0; mt < 4; mt++) {
#pragma unroll
            for (int half = 0; half < 2; half++) {
                int i = i0 + wm * 64 + mt * 16 + g + half * 8;
                float rs = 0.f;
#pragma unroll
                for (int nt = 0; nt < 4; nt++) {
                    int j = j0 + wn * 32 + nt * 8 + t4 * 2;
                    float e0 = __expf(acc[mt][nt][half * 2 + 0]);
                    float e1 = __expf(acc[mt][nt][half * 2 + 1]);
                    *(float2*)(Cp + (long)i * Cs0 + j) = make_float2(e0, e1);
                    rs += e0 + e1;
                }
                rs += __shfl_xor_sync(0xffffffffu, rs, 1);
                rs += __shfl_xor_sync(0xffffffffu, rs, 2);
                if (t4 == 0) atomicAdd(&rowsum[i], rs);
            }
        }
        return;
    }
#pragma unroll
    for (int mt = 0; mt < 4; mt++) {
#pragma unroll
        for (int half = 0; half < 2; half++) {
            int i = i0 + wm * 64 + mt * 16 + g + half * 8;
            float bi = bias ? scale * bias[i] : 0.f;
            float rs = 0.f, rq = 0.f;
#pragma unroll
            for (int nt = 0; nt < 4; nt++) {
                int j = j0 + wn * 32 + nt * 8 + t4 * 2;
                long off = (long)i * Cs0 + j;
                float2 v;
                v.x = scale * acc[mt][nt][half * 2 + 0];
                v.y = scale * acc[mt][nt][half * 2 + 1];
                if (colscale) {
                    v.x *= colscale[j];
                    v.y *= colscale[j + 1];
                }
                v.x += bi; v.y += bi;
                if (cbias) {
                    v.x += scale * cbias[j];
                    v.y += scale * cbias[j + 1];
                }
                if (addend) {
                    float2 a2 = *(const float2*)(addend + off);
                    v.x += a2.x; v.y += a2.y;
                }
                *(float2*)(Cp + off) = v;
                if (chansum) {
                    rs += v.x + v.y;
                    rq += v.x * v.x + v.y * v.y;
                }
            }
            if (chansum) {
                rs += __shfl_xor_sync(0xffffffffu, rs, 1);
                rs += __shfl_xor_sync(0xffffffffu, rs, 2);
                rq += __shfl_xor_sync(0xffffffffu, rq, 1);
                rq += __shfl_xor_sync(0xffffffffu, rq, 2);
                if (t4 == 0) {
                    atomicAdd(&chansum[i], rs);
                    atomicAdd(&chansum[C_ + i], rq);
                }
            }
        }
    }
}

// ---------------- pack [Wq_s; Wq_g] and biases ----------------
__global__ void packq_kernel(const float* __restrict__ Wqs,
                             const float* __restrict__ bqs,
                             const float* __restrict__ Wqg,
                             const float* __restrict__ bqg) {
    int r = blockIdx.x;  // 0..511
    int c = threadIdx.x;
    g_Wq2[r * C_ + c] = (r < C_) ? Wqs[r * C_ + c] : Wqg[(r - C_) * C_ + c];
    if (c == 0) g_bq2[r] = (r < C_) ? bqs[r] : bqg[r - C_];
}

// ---------------- bov = Wo @ bv (per attention) ----------------
__global__ void bov_kernel(const float* __restrict__ Wo,
                           const float* __restrict__ bv, int a) {
    int e = threadIdx.x;  // 256 threads
    const float* row = Wo + e * C_;
    float s = 0.f;
#pragma unroll 8
    for (int c = 0; c < C_; c++) s += row[c] * bv[c];
    g_bov[a * C_ + e] = s;
}

// ---------------- invert softmax denominators in place ----------------
__global__ void invden_kernel(int a) {
    int i = blockIdx.x * 256 + threadIdx.x;
    g_den[a * B_ * N_ + i] = 1.f / g_den[a * B_ * N_ + i];
}

// ---------------- finalize channel stats ----------------
__global__ void statfin_kernel() {
    int d = threadIdx.x;
    const float invBN = 1.f / (float)(B_ * N_);
    float mu = g_cs[d] * invBN;
    float var = g_cs[C_ + d] * invBN - mu * mu;
    g_mu[d] = mu;
    g_rstd[d] = rsqrtf(var + EPS_);
}

// ---------------- mean over N per (b,c) ----------------
__global__ void mean_kernel(const float* __restrict__ x) {
    int bc = blockIdx.x;
    const float* row = x + (size_t)bc * N_;
    float s = 0.f;
    for (int n = threadIdx.x; n < N_; n += 256) s += row[n];
    __shared__ float sh[256];
    sh[threadIdx.x] = s;
    __syncthreads();
    for (int o = 128; o > 0; o >>= 1) {
        if (threadIdx.x < o) sh[threadIdx.x] += sh[threadIdx.x + o];
        __syncthreads();
    }
    if (threadIdx.x == 0) g_mean[bc] = sh[0] * (1.f / N_);
}

// ------- variation score per (b,n); zeros denominators + stat accum -------
__global__ void score_kernel(const float* __restrict__ x) {
    int b = blockIdx.y;
    int n = blockIdx.x * 256 + threadIdx.x;
    const float* xb = x + (size_t)b * C_ * N_;
    const float* mb = g_mean + b * C_;
    float acc = 0.f;
#pragma unroll 4
    for (int c = 0; c < C_; c++) {
        float v = xb[(size_t)c * N_ + n] - mb[c];
        acc += v * v;
    }
    int gi = b * N_ + n;
    g_score[gi] = acc;
    g_den[gi] = 0.f;
    g_den[B_ * N_ + gi] = 0.f;
    if (gi < 2 * C_) g_cs[gi] = 0.f;
}

// ---------------- per-batch bitonic full sort ----------------
__global__ void topk_kernel() {
    __shared__ float sk[N_];
    __shared__ int   sv[N_];
    int b = blockIdx.x;
    int t = threadIdx.x;
    for (int i = t; i < N_; i += 1024) {
        sk[i] = g_score[b * N_ + i];
        sv[i] = i;
    }
    __syncthreads();
    for (int k = 2; k <= N_; k <<= 1) {
        for (int j = k >> 1; j > 0; j >>= 1) {
            for (int i = t; i < N_; i += 1024) {
                int ixj = i ^ j;
                if (ixj > i) {
                    bool up = ((i & k) == 0);
                    float a = sk[i], c = sk[ixj];
                    bool sw = up ? (a > c) : (a < c);
                    if (sw) {
                        sk[i] = c; sk[ixj] = a;
                        int tv = sv[i]; sv[i] = sv[ixj]; sv[ixj] = tv;
                    }
                }
            }
            __syncthreads();
        }
    }
    if (t < M_) {
        g_idx[b * 2 * M_ + t]      = sv[N_ - 1 - t];  // sharp
        g_idx[b * 2 * M_ + M_ + t] = sv[t];           // gentle
    }
}

// ---------------- gather selected columns (both sets in one launch) -------
__global__ void gather_kernel(const float* __restrict__ x) {
    int m = blockIdx.x * 256 + threadIdx.x;
    int c = blockIdx.y;
    int b = blockIdx.z >> 1;
    int which = blockIdx.z & 1;
    const int* idx = g_idx + b * 2 * M_ + which * M_;
    float v = x[((size_t)b * C_ + c) * N_ + idx[m]];
    float* dst = which ? g_Xg : g_Xs;
    dst[((size_t)b * C_ + c) * M_ + m] = v;
}

// ---------------- BN + ReLU (float4) ----------------
__global__ void bnrelu_kernel(const float* __restrict__ gamma,
                              const float* __restrict__ beta,
                              float* __restrict__ out) {
    size_t i4 = (size_t)blockIdx.x * 256 + threadIdx.x;  // float4 index
    size_t i = i4 * 4;
    int d = (int)((i / N_) % C_);
    float sc = g_rstd[d] * gamma[d];
    float sh = beta[d] - g_mu[d] * sc;
    float4 z = *(const float4*)(g_Z + i);
    float4 v;
    v.x = fmaxf(z.x * sc + sh, 0.f);
    v.y = fmaxf(z.y * sc + sh, 0.f);
    v.z = fmaxf(z.z * sc + sh, 0.f);
    v.w = fmaxf(z.w * sc + sh, 0.f);
    *(float4*)(out + i) = v;
}

// ---------------- host side ------------------------------------------------
static float* sym_f(const void* s) {
    void* p = nullptr;
    cudaGetSymbolAddress(&p, s);
    return (float*)p;
}

static constexpr int GEMM_SMEM = NSTAGE * 2 * OPW * 4;  // 110592 bytes

static void launch_tc(const float* A, long Ab, long As0, long As1,
                      const float* Bp, long Bb, long Bs0, long Bs1,
                      float* Cp, long Cb, long Cs0,
                      const float* bias, const float* cbias,
                      const float* addend, long Addb,
                      float* rowsum, long Rsb,
                      const float* colscale, long Csb,
                      float* chansum,
                      float scale, int Md, int Nd, int Kd, int nbatch) {
    dim3 grid(Nd / BN, Md / BM, nbatch);
    tc_gemm_kernel<<<grid, 256, GEMM_SMEM>>>(
        A, Ab, As0, As1, Bp, Bb, Bs0, Bs1, Cp, Cb, Cs0,
        bias, cbias, addend, Addb, rowsum, Rsb, colscale, Csb, chansum,
        scale, Kd);
}

extern "C" void kernel_launch(void* const* d_in, const int* in_sizes, int n_in,
                              void* d_out, int out_size) {
    static bool attr_done = false;
    if (!attr_done) {
        cudaFuncSetAttribute(tc_gemm_kernel,
                             cudaFuncAttributeMaxDynamicSharedMemorySize, GEMM_SMEM);
        attr_done = true;
    }

    const float* P[24];
    int p = 0;
    for (int i = 0; i < n_in && p < 24; i++) {
        if (in_sizes[i] == 1) continue;  // num_select scalar
        P[p++] = (const float*)d_in[i];
    }
    const float* x = P[0];
    const float* Wq[2] = {P[1], P[9]};
    const float* bq[2] = {P[2], P[10]};
    const float* Wk[2] = {P[3], P[11]};
    const float* bk[2] = {P[4], P[12]};
    const float* Wv[2] = {P[5], P[13]};
    const float* bv[2] = {P[6], P[14]};
    const float* Wo[2] = {P[7], P[15]};
    const float* bo[2] = {P[8], P[16]};
    const float* Wf = P[17];
    const float* bf = P[18];
    const float* gamma = P[19];
    const float* beta = P[20];
    float* out = (float*)d_out;

    float* Q   = sym_f(g_Q);
    float* K   = sym_f(g_K);
    float* WV  = sym_f(g_WV);
    float* S   = sym_f(g_S);
    float* Xs  = sym_f(g_Xs);
    float* Xg  = sym_f(g_Xg);
    float* y2  = sym_f(g_y2);
    float* Z   = sym_f(g_Z);
    float* den = sym_f(g_den);
    float* Wow = sym_f(g_Wow);
    float* bov = sym_f(g_bov);
    float* Wq2 = sym_f(g_Wq2);
    float* bq2 = sym_f(g_bq2);
    float* cs  = sym_f(g_cs);

    const long xB = (long)C_ * N_;
    const long cM = (long)C_ * M_;
    const long sB = (long)N_ * M_;
    const long qB = (long)N_ * 2 * C_;
    const long yB = (long)2 * C_ * N_;

    // 1) geometry disentangle
    mean_kernel<<<B_ * C_, 256>>>(x);
    score_kernel<<<dim3(N_ / 256, B_), 256>>>(x);  // zeros g_den + g_cs
    topk_kernel<<<B_, 1024>>>();
    gather_kernel<<<dim3(M_ / 256, C_, 2 * B_), 256>>>(x);

    // 2) merged Q projection for both attentions
    packq_kernel<<<2 * C_, 256>>>(Wq[0], bq[0], Wq[1], bq[1]);
    launch_tc(x, xB, 1, N_, Wq2, 0, C_, 1, Q, qB, 2 * C_,
              nullptr, bq2, nullptr, 0, nullptr, 0, nullptr, 0, nullptr,
              0.0625f, N_, 2 * C_, C_, B_);

    // 3) two cross-attentions
    for (int a = 0; a < 2; a++) {
        const float* Xctx = (a == 0) ? Xs : Xg;
        float* ybuf = y2 + (size_t)a * C_ * N_;
        float* dena = den + a * B_ * N_;
        float* Wowa = Wow + a * C_ * C_;
        float* bova = bov + a * C_;

        // Kt[m,d] = sum_c Xctx[c,m] Wk[d,c] + bk[d]
        launch_tc(Xctx, cM, 1, M_, Wk[a], 0, C_, 1, K, (long)M_ * C_, C_,
                  nullptr, bk[a], nullptr, 0, nullptr, 0, nullptr, 0, nullptr,
                  1.f, M_, C_, C_, B_);
        // Wow[e,c2] = sum_c Wo[e,c] Wv[c,c2]
        launch_tc(Wo[a], 0, C_, 1, Wv[a], 0, 1, C_, Wowa, 0, C_,
                  nullptr, nullptr, nullptr, 0, nullptr, 0, nullptr, 0, nullptr,
                  1.f, C_, C_, C_, 1);
        bov_kernel<<<1, 256>>>(Wo[a], bv[a], a);
        // E[n,m] = exp(sum_d Q[n, a*256+d] Kt[m,d]); den += row sums
        launch_tc(Q + a * C_, qB, 2 * C_, 1, K, (long)M_ * C_, C_, 1, S, sB, M_,
                  nullptr, nullptr, nullptr, 0, dena, N_, nullptr, 0, nullptr,
                  1.f, N_, M_, C_, B_);
        invden_kernel<<<(B_ * N_) / 256, 256>>>(a);
        // WV[e,m] = Wow@Xctx + bov
        launch_tc(Wowa, 0, C_, 1, Xctx, cM, 1, M_, WV, cM, M_,
                  bova, nullptr, nullptr, 0, nullptr, 0, nullptr, 0, nullptr,
                  1.f, C_, M_, C_, B_);
        // y2[b][a*C+e][n] = (sum_m WV[e,m] E[n,m]) * invden[b,n] + bo[e] + x[e,n]
        launch_tc(WV, cM, M_, 1, S, sB, M_, 1, ybuf, yB, N_,
                  bo[a], nullptr, x, xB, nullptr, 0, dena, N_, nullptr,
                  1.f, C_, N_, M_, B_);
    }

    // 4) fuse (single GEMM, K=512): Z = Wf @ y2 + bf; stats in epilogue
    launch_tc(Wf, 0, 2 * C_, 1, y2, yB, 1, N_, Z, xB, N_,
              bf, nullptr, nullptr, 0, nullptr, 0, nullptr, 0, cs,
              1.f, C_, N_, 2 * C_, B_);

    // 5) batch-norm (training stats) + ReLU
    statfin_kernel<<<1, 256>>>();
    bnrelu_kernel<<<(B_ * C_ * N_) / 1024, 256>>>(gamma, beta, out);
}

// round 12
// speedup vs baseline: 1.4287x; 1.2961x over previous
#include <cuda_runtime.h>
#include <cuda_bf16.h>
#include <cstdint>
#include <math.h>

// Problem dims (fixed by the reference)
static constexpr int B_ = 16;
static constexpr int C_ = 256;
static constexpr int N_ = 4096;
static constexpr int M_ = 1024;
static constexpr float EPS_ = 1e-5f;

// ---------------- scratch (static device globals; no allocation) ----------
__device__ float g_mean[B_ * C_];
__device__ float g_score[B_ * N_];
__device__ int   g_idx[B_ * 2 * M_];
__device__ float g_Xs[(size_t)B_ * C_ * M_];
__device__ float g_Xg[(size_t)B_ * C_ * M_];
__device__ __nv_bfloat16 g_Qh[(size_t)B_ * N_ * 2 * C_]; // Q^T both: [n][2C]
__device__ __nv_bfloat16 g_Kh[(size_t)B_ * M_ * C_];     // K^T: [m][d]
__device__ __nv_bfloat16 g_WVh[(size_t)B_ * C_ * M_];    // [c][m]
__device__ __nv_bfloat16 g_Sh[(size_t)B_ * N_ * M_];     // E = exp(scores)
__device__ float g_y2[(size_t)B_ * 2 * C_ * N_];// [b][2C][n]
__device__ float g_Z[(size_t)B_ * C_ * N_];
__device__ float g_den[2 * B_ * N_];
__device__ float g_Wow[2 * C_ * C_];
__device__ float g_bov[2 * C_];
__device__ float g_Wq2[2 * C_ * C_];
__device__ float g_bq2[2 * C_];
__device__ float g_cs[2 * C_];
__device__ float g_mu[C_];
__device__ float g_rstd[C_];

// ---------------- helpers --------------------------------------------------
__device__ __forceinline__ void mma_tf32(float* c, const uint32_t* a, const uint32_t* b) {
    asm volatile(
        "mma.sync.aligned.m16n8k8.row.col.f32.tf32.tf32.f32 "
        "{%0,%1,%2,%3}, {%4,%5,%6,%7}, {%8,%9}, {%0,%1,%2,%3};"
        : "+f"(c[0]), "+f"(c[1]), "+f"(c[2]), "+f"(c[3])
        : "r"(a[0]), "r"(a[1]), "r"(a[2]), "r"(a[3]), "r"(b[0]), "r"(b[1]));
}
__device__ __forceinline__ void mma_bf16(float* c, const uint32_t* a, const uint32_t* b) {
    asm volatile(
        "mma.sync.aligned.m16n8k16.row.col.f32.bf16.bf16.f32 "
        "{%0,%1,%2,%3}, {%4,%5,%6,%7}, {%8,%9}, {%0,%1,%2,%3};"
        : "+f"(c[0]), "+f"(c[1]), "+f"(c[2]), "+f"(c[3])
        : "r"(a[0]), "r"(a[1]), "r"(a[2]), "r"(a[3]), "r"(b[0]), "r"(b[1]));
}
__device__ __forceinline__ void ldsm_x4(uint32_t& r0, uint32_t& r1,
                                        uint32_t& r2, uint32_t& r3, uint32_t addr) {
    asm volatile("ldmatrix.sync.aligned.m8n8.x4.shared.b16 {%0,%1,%2,%3}, [%4];"
                 : "=r"(r0), "=r"(r1), "=r"(r2), "=r"(r3) : "r"(addr));
}
__device__ __forceinline__ uint32_t smem_u32(const void* p) {
    uint32_t a;
    asm("{ .reg .u64 t; cvta.to.shared.u64 t, %1; cvt.u32.u64 %0, t; }"
        : "=r"(a) : "l"(p));
    return a;
}
__device__ __forceinline__ void cp16(uint32_t saddr, const void* g) {
    asm volatile("cp.async.cg.shared.global [%0], [%1], 16;" :: "r"(saddr), "l"(g));
}

// ================== pipelined warp-MMA generic strided GEMM ================
// half_mode=0: fp32 data, tf32 MMA (k-contig via ldmatrix, other via LDS).
// half_mode=1: bf16 data, m16n8k16 MMA; BOTH operands must be k-contig.
// Normal: D = scale*acc [*colscale[j]] + scale*(bias[i]+cbias[j]) [+addend]
//         ; out_bf16 writes bf16; chansum accumulates per-channel sum/sumsq
// Exp mode (rowsum != nullptr): D = exp(acc) -> bf16; rowsum[i] += sums
// 256 threads, 8 warps 2x4 (warp tile 64x32), block 128x128, BK=32, 3 stages.
#define BM 128
#define BN 128
#define BK 32
#define NSTAGE 3
#define SKC 36    // fp32 k-contig row stride (words)
#define SIC 136   // fp32 i-contig row stride (words)
#define OPW 4608  // fp32 words per operand per stage
#define SKH 40    // bf16 k-contig row stride (elements); 80B, 16B-aligned rows
#define HOPB 10240 // bf16 bytes per operand per stage (128*40*2)

__device__ __forceinline__ void stage_tile(const float* __restrict__ src,
                                           long s0, long s1, int kc,
                                           uint32_t sbase, int t0, int kt, int tid) {
    if (kc) {
#pragma unroll
        for (int it = 0; it < 4; it++) {
            int q = tid + it * 256;
            int row = q >> 3, kq = (q & 7) << 2;
            cp16(sbase + (uint32_t)(row * SKC + kq) * 4u,
                 src + (long)(t0 + row) * s0 + kt + kq);
        }
    } else {
#pragma unroll
        for (int it = 0; it < 4; it++) {
            int q = tid + it * 256;
            int kr = q >> 5, iq = (q & 31) << 2;
            cp16(sbase + (uint32_t)(kr * SIC + iq) * 4u,
                 src + (long)(t0 + iq) + (long)(kt + kr) * s1);
        }
    }
}

__device__ __forceinline__ void stage_tile_h(const __nv_bfloat16* __restrict__ src,
                                             long s0, uint32_t sbase,
                                             int t0, int kt, int tid) {
    // 128 rows x 32 bf16, k-contig; 16B = 8 bf16 per cp
#pragma unroll
    for (int it = 0; it < 2; it++) {
        int q = tid + it * 256;
        int row = q >> 2, kq = (q & 3) << 3;
        cp16(sbase + (uint32_t)(row * SKH + kq) * 2u,
             src + (long)(t0 + row) * s0 + kt + kq);
    }
}

__global__ void __launch_bounds__(256, 2)
tc_gemm_kernel(const float* __restrict__ A, long Ab, long As0, long As1,
               const float* __restrict__ Bp, long Bb, long Bs0, long Bs1,
               float* __restrict__ Cp, long Cb, long Cs0,
               const float* __restrict__ bias,
               const float* __restrict__ cbias,
               const float* __restrict__ addend, long Addb,
               float* rowsum, long Rsb,
               const float* __restrict__ colscale, long Csb,
               float* chansum,
               float scale, int Kd, int half_mode, int out_bf16) {
    extern __shared__ uint32_t sm[];

    const int tid = threadIdx.x;
    const int wid = tid >> 5;
    const int lane = tid & 31;
    const int g = lane >> 2;
    const int t4 = lane & 3;
    const int wm = wid & 1;
    const int wn = wid >> 1;
    const int tr = lane & 7;
    const int tq = lane >> 3;

    const int aKc = (As1 == 1);
    const int bKc = (Bs1 == 1);

    const int bz = blockIdx.z;
    const size_t aoff = (size_t)bz * Ab, boff = (size_t)bz * Bb, coff = (size_t)bz * Cb;
    const float* Af = A + aoff;
    const float* Bf = Bp + boff;
    const __nv_bfloat16* Ah = (const __nv_bfloat16*)A + aoff;
    const __nv_bfloat16* Bh = (const __nv_bfloat16*)Bp + boff;
    float* Cf = Cp + coff;
    __nv_bfloat16* Ch = (__nv_bfloat16*)Cp + coff;
    if (addend) addend += (size_t)bz * Addb;
    if (rowsum) rowsum += (size_t)bz * Rsb;
    if (colscale) colscale += (size_t)bz * Csb;

    const int i0 = blockIdx.y * BM;
    const int j0 = blockIdx.x * BN;

    const uint32_t smbase = smem_u32(sm);
    const uint32_t aOff = (uint32_t)((wm * 64 + (tq & 1) * 8 + tr) * SKC + (tq >> 1) * 4) * 4u;
    const uint32_t bOff = (uint32_t)((wn * 32 + (tq >> 1) * 8 + tr) * SKC + (tq & 1) * 4) * 4u;
    const uint32_t aOffH = (uint32_t)((wm * 64 + (tq & 1) * 8 + tr) * SKH) * 2u + (tq >> 1) * 16u;
    const uint32_t bOffH = (uint32_t)((wn * 32 + (tq >> 1) * 8 + tr) * SKH) * 2u + (tq & 1) * 16u;

    float acc[4][4][4];
#pragma unroll
    for (int a = 0; a < 4; a++)
#pragma unroll
        for (int b = 0; b < 4; b++)
#pragma unroll
            for (int c = 0; c < 4; c++) acc[a][b][c] = 0.f;

    const int nch = Kd >> 5;
    const uint32_t stageBytes = half_mode ? (2u * HOPB) : (uint32_t)(2 * OPW * 4);
    const uint32_t opBytes = half_mode ? (uint32_t)HOPB : (uint32_t)(OPW * 4);

    // prologue: stage chunks 0,1
    if (half_mode) {
        stage_tile_h(Ah, As0, smbase, i0, 0, tid);
        stage_tile_h(Bh, Bs0, smbase + opBytes, j0, 0, tid);
    } else {
        stage_tile(Af, As0, As1, aKc, smbase, i0, 0, tid);
        stage_tile(Bf, Bs0, Bs1, bKc, smbase + opBytes, j0, 0, tid);
    }
    asm volatile("cp.async.commit_group;" ::: "memory");
    if (nch > 1) {
        uint32_t sb1 = smbase + stageBytes;
        if (half_mode) {
            stage_tile_h(Ah, As0, sb1, i0, BK, tid);
            stage_tile_h(Bh, Bs0, sb1 + opBytes, j0, BK, tid);
        } else {
            stage_tile(Af, As0, As1, aKc, sb1, i0, BK, tid);
            stage_tile(Bf, Bs0, Bs1, bKc, sb1 + opBytes, j0, BK, tid);
        }
    }
    asm volatile("cp.async.commit_group;" ::: "memory");

    int st = 0, stw = 2;
    for (int ch = 0; ch < nch; ch++) {
        asm volatile("cp.async.wait_group 1;" ::: "memory");
        __syncthreads();

        const uint32_t sAu = smbase + st * stageBytes;
        const uint32_t sBu = sAu + opBytes;

        if (half_mode) {
#pragma unroll
            for (int ks = 0; ks < BK; ks += 16) {
                uint32_t af[4][4];
#pragma unroll
                for (int mt = 0; mt < 4; mt++)
                    ldsm_x4(af[mt][0], af[mt][1], af[mt][2], af[mt][3],
                            sAu + aOffH + (uint32_t)(mt * 16 * SKH + ks) * 2u);
                uint32_t bf[4][2];
#pragma unroll
                for (int p = 0; p < 2; p++)
                    ldsm_x4(bf[2 * p][0], bf[2 * p][1], bf[2 * p + 1][0], bf[2 * p + 1][1],
                            sBu + bOffH + (uint32_t)(p * 16 * SKH + ks) * 2u);
#pragma unroll
                for (int mt = 0; mt < 4; mt++)
#pragma unroll
                    for (int nt = 0; nt < 4; nt++)
                        mma_bf16(acc[mt][nt], af[mt], bf[nt]);
            }
        } else {
            const uint32_t* sA = sm + (sAu - smbase) / 4;
            const uint32_t* sB = sA + OPW;
#pragma unroll
            for (int ks = 0; ks < BK; ks += 8) {
                uint32_t af[4][4];
                if (aKc) {
#pragma unroll
                    for (int mt = 0; mt < 4; mt++)
                        ldsm_x4(af[mt][0], af[mt][1], af[mt][2], af[mt][3],
                                sAu + aOff + (uint32_t)(mt * 16 * SKC + ks) * 4u);
                } else {
#pragma unroll
                    for (int mt = 0; mt < 4; mt++) {
                        int rb = wm * 64 + mt * 16 + g;
                        af[mt][0] = sA[(ks + t4    ) * SIC + rb    ];
                        af[mt][1] = sA[(ks + t4    ) * SIC + rb + 8];
                        af[mt][2] = sA[(ks + t4 + 4) * SIC + rb    ];
                        af[mt][3] = sA[(ks + t4 + 4) * SIC + rb + 8];
                    }
                }
                uint32_t bf[4][2];
                if (bKc) {
#pragma unroll
                    for (int p = 0; p < 2; p++)
                        ldsm_x4(bf[2 * p][0], bf[2 * p][1], bf[2 * p + 1][0], bf[2 * p + 1][1],
                                sBu + bOff + (uint32_t)(p * 16 * SKC + ks) * 4u);
                } else {
#pragma unroll
                    for (int nt = 0; nt < 4; nt++) {
                        int cb = wn * 32 + nt * 8 + g;
                        bf[nt][0] = sB[(ks + t4    ) * SIC + cb];
                        bf[nt][1] = sB[(ks + t4 + 4) * SIC + cb];
                    }
                }
#pragma unroll
                for (int mt = 0; mt < 4; mt++)
#pragma unroll
                    for (int nt = 0; nt < 4; nt++)
                        mma_tf32(acc[mt][nt], af[mt], bf[nt]);
            }
        }

        if (ch + 2 < nch) {
            uint32_t sb = smbase + stw * stageBytes;
            if (half_mode) {
                stage_tile_h(Ah, As0, sb, i0, (ch + 2) * BK, tid);
                stage_tile_h(Bh, Bs0, sb + opBytes, j0, (ch + 2) * BK, tid);
            } else {
                stage_tile(Af, As0, As1, aKc, sb, i0, (ch + 2) * BK, tid);
                stage_tile(Bf, Bs0, Bs1, bKc, sb + opBytes, j0, (ch + 2) * BK, tid);
            }
        }
        asm volatile("cp.async.commit_group;" ::: "memory");

        if (++st == NSTAGE) st = 0;
        if (++stw == NSTAGE) stw = 0;
    }

    // ---- epilogue ----
    if (rowsum) {
        // exp mode: bf16 output + row sums
#pragma unroll
        for (int mt = 0; mt < 4; mt++) {
#pragma unroll
            for (int half = 0; half < 2; half++) {
                int i = i0 + wm * 64 + mt * 16 + g + half * 8;
                float rs = 0.f;
#pragma unroll
                for (int nt = 0; nt < 4; nt++) {
                    int j = j0 + wn * 32 + nt * 8 + t4 * 2;
                    float e0 = __expf(acc[mt][nt][half * 2 + 0]);
                    float e1 = __expf(acc[mt][nt][half * 2 + 1]);
                    *(__nv_bfloat162*)(Ch + (long)i * Cs0 + j) =
                        __floats2bfloat162_rn(e0, e1);
                    rs += e0 + e1;
                }
                rs += __shfl_xor_sync(0xffffffffu, rs, 1);
                rs += __shfl_xor_sync(0xffffffffu, rs, 2);
                if (t4 == 0) atomicAdd(&rowsum[i], rs);
            }
        }
        return;
    }
#pragma unroll
    for (int mt = 0; mt < 4; mt++) {
#pragma unroll
        for (int half = 0; half < 2; half++) {
            int i = i0 + wm * 64 + mt * 16 + g + half * 8;
            float bi = bias ? scale * bias[i] : 0.f;
            float rs = 0.f, rq = 0.f;
#pragma unroll
            for (int nt = 0; nt < 4; nt++) {
                int j = j0 + wn * 32 + nt * 8 + t4 * 2;
                long off = (long)i * Cs0 + j;
                float2 v;
                v.x = scale * acc[mt][nt][half * 2 + 0];
                v.y = scale * acc[mt][nt][half * 2 + 1];
                if (colscale) {
                    v.x *= colscale[j];
                    v.y *= colscale[j + 1];
                }
                v.x += bi; v.y += bi;
                if (cbias) {
                    v.x += scale * cbias[j];
                    v.y += scale * cbias[j + 1];
                }
                if (addend) {
                    float2 a2 = *(const float2*)(addend + off);
                    v.x += a2.x; v.y += a2.y;
                }
                if (out_bf16) {
                    *(__nv_bfloat162*)(Ch + off) = __floats2bfloat162_rn(v.x, v.y);
                } else {
                    *(float2*)(Cf + off) = v;
                }
                if (chansum) {
                    rs += v.x + v.y;
                    rq += v.x * v.x + v.y * v.y;
                }
            }
            if (chansum) {
                rs += __shfl_xor_sync(0xffffffffu, rs, 1);
                rs += __shfl_xor_sync(0xffffffffu, rs, 2);
                rq += __shfl_xor_sync(0xffffffffu, rq, 1);
                rq += __shfl_xor_sync(0xffffffffu, rq, 2);
                if (t4 == 0) {
                    atomicAdd(&chansum[i], rs);
                    atomicAdd(&chansum[C_ + i], rq);
                }
            }
        }
    }
}

// ---------------- pack [Wq_s; Wq_g] and biases ----------------
__global__ void packq_kernel(const float* __restrict__ Wqs,
                             const float* __restrict__ bqs,
                             const float* __restrict__ Wqg,
                             const float* __restrict__ bqg) {
    int r = blockIdx.x;
    int c = threadIdx.x;
    g_Wq2[r * C_ + c] = (r < C_) ? Wqs[r * C_ + c] : Wqg[(r - C_) * C_ + c];
    if (c == 0) g_bq2[r] = (r < C_) ? bqs[r] : bqg[r - C_];
}

// ---------------- bov = Wo @ bv (per attention) ----------------
__global__ void bov_kernel(const float* __restrict__ Wo,
                           const float* __restrict__ bv, int a) {
    int e = threadIdx.x;
    const float* row = Wo + e * C_;
    float s = 0.f;
#pragma unroll 8
    for (int c = 0; c < C_; c++) s += row[c] * bv[c];
    g_bov[a * C_ + e] = s;
}

// ---------------- invert softmax denominators in place ----------------
__global__ void invden_kernel(int a) {
    int i = blockIdx.x * 256 + threadIdx.x;
    g_den[a * B_ * N_ + i] = 1.f / g_den[a * B_ * N_ + i];
}

// ---------------- finalize channel stats ----------------
__global__ void statfin_kernel() {
    int d = threadIdx.x;
    const float invBN = 1.f / (float)(B_ * N_);
    float mu = g_cs[d] * invBN;
    float var = g_cs[C_ + d] * invBN - mu * mu;
    g_mu[d] = mu;
    g_rstd[d] = rsqrtf(var + EPS_);
}

// ---------------- mean over N per (b,c) ----------------
__global__ void mean_kernel(const float* __restrict__ x) {
    int bc = blockIdx.x;
    const float* row = x + (size_t)bc * N_;
    float s = 0.f;
    for (int n = threadIdx.x; n < N_; n += 256) s += row[n];
    __shared__ float sh[256];
    sh[threadIdx.x] = s;
    __syncthreads();
    for (int o = 128; o > 0; o >>= 1) {
        if (threadIdx.x < o) sh[threadIdx.x] += sh[threadIdx.x + o];
        __syncthreads();
    }
    if (threadIdx.x == 0) g_mean[bc] = sh[0] * (1.f / N_);
}

// ------- variation score per (b,n); zeros denominators + stat accum -------
__global__ void score_kernel(const float* __restrict__ x) {
    int b = blockIdx.y;
    int n = blockIdx.x * 256 + threadIdx.x;
    const float* xb = x + (size_t)b * C_ * N_;
    const float* mb = g_mean + b * C_;
    float acc = 0.f;
#pragma unroll 4
    for (int c = 0; c < C_; c++) {
        float v = xb[(size_t)c * N_ + n] - mb[c];
        acc += v * v;
    }
    int gi = b * N_ + n;
    g_score[gi] = acc;
    g_den[gi] = 0.f;
    g_den[B_ * N_ + gi] = 0.f;
    if (gi < 2 * C_) g_cs[gi] = 0.f;
}

// ---------------- per-batch bitonic full sort ----------------
__global__ void topk_kernel() {
    __shared__ float sk[N_];
    __shared__ int   sv[N_];
    int b = blockIdx.x;
    int t = threadIdx.x;
    for (int i = t; i < N_; i += 1024) {
        sk[i] = g_score[b * N_ + i];
        sv[i] = i;
    }
    __syncthreads();
    for (int k = 2; k <= N_; k <<= 1) {
        for (int j = k >> 1; j > 0; j >>= 1) {
            for (int i = t; i < N_; i += 1024) {
                int ixj = i ^ j;
                if (ixj > i) {
                    bool up = ((i & k) == 0);
                    float a = sk[i], c = sk[ixj];
                    bool sw = up ? (a > c) : (a < c);
                    if (sw) {
                        sk[i] = c; sk[ixj] = a;
                        int tv = sv[i]; sv[i] = sv[ixj]; sv[ixj] = tv;
                    }
                }
            }
            __syncthreads();
        }
    }
    if (t < M_) {
        g_idx[b * 2 * M_ + t]      = sv[N_ - 1 - t];  // sharp
        g_idx[b * 2 * M_ + M_ + t] = sv[t];           // gentle
    }
}

// ---------------- gather selected columns (both sets in one launch) -------
__global__ void gather_kernel(const float* __restrict__ x) {
    int m = blockIdx.x * 256 + threadIdx.x;
    int c = blockIdx.y;
    int b = blockIdx.z >> 1;
    int which = blockIdx.z & 1;
    const int* idx = g_idx + b * 2 * M_ + which * M_;
    float v = x[((size_t)b * C_ + c) * N_ + idx[m]];
    float* dst = which ? g_Xg : g_Xs;
    dst[((size_t)b * C_ + c) * M_ + m] = v;
}

// ---------------- BN + ReLU (float4) ----------------
__global__ void bnrelu_kernel(const float* __restrict__ gamma,
                              const float* __restrict__ beta,
                              float* __restrict__ out) {
    size_t i4 = (size_t)blockIdx.x * 256 + threadIdx.x;
    size_t i = i4 * 4;
    int d = (int)((i / N_) % C_);
    float sc = g_rstd[d] * gamma[d];
    float sh = beta[d] - g_mu[d] * sc;
    float4 z = *(const float4*)(g_Z + i);
    float4 v;
    v.x = fmaxf(z.x * sc + sh, 0.f);
    v.y = fmaxf(z.y * sc + sh, 0.f);
    v.z = fmaxf(z.z * sc + sh, 0.f);
    v.w = fmaxf(z.w * sc + sh, 0.f);
    *(float4*)(out + i) = v;
}

// ---------------- host side ------------------------------------------------
static float* sym_f(const void* s) {
    void* p = nullptr;
    cudaGetSymbolAddress(&p, s);
    return (float*)p;
}

static constexpr int GEMM_SMEM = NSTAGE * 2 * OPW * 4;  // 110592 bytes

static void launch_tc(const float* A, long Ab, long As0, long As1,
                      const float* Bp, long Bb, long Bs0, long Bs1,
                      float* Cp, long Cb, long Cs0,
                      const float* bias, const float* cbias,
                      const float* addend, long Addb,
                      float* rowsum, long Rsb,
                      const float* colscale, long Csb,
                      float* chansum,
                      float scale, int Md, int Nd, int Kd, int nbatch,
                      int half_mode, int out_bf16) {
    dim3 grid(Nd / BN, Md / BM, nbatch);
    tc_gemm_kernel<<<grid, 256, GEMM_SMEM>>>(
        A, Ab, As0, As1, Bp, Bb, Bs0, Bs1, Cp, Cb, Cs0,
        bias, cbias, addend, Addb, rowsum, Rsb, colscale, Csb, chansum,
        scale, Kd, half_mode, out_bf16);
}

extern "C" void kernel_launch(void* const* d_in, const int* in_sizes, int n_in,
                              void* d_out, int out_size) {
    static bool attr_done = false;
    if (!attr_done) {
        cudaFuncSetAttribute(tc_gemm_kernel,
                             cudaFuncAttributeMaxDynamicSharedMemorySize, GEMM_SMEM);
        attr_done = true;
    }

    const float* P[24];
    int p = 0;
    for (int i = 0; i < n_in && p < 24; i++) {
        if (in_sizes[i] == 1) continue;  // num_select scalar
        P[p++] = (const float*)d_in[i];
    }
    const float* x = P[0];
    const float* Wq[2] = {P[1], P[9]};
    const float* bq[2] = {P[2], P[10]};
    const float* Wk[2] = {P[3], P[11]};
    const float* bk[2] = {P[4], P[12]};
    const float* Wv[2] = {P[5], P[13]};
    const float* bv[2] = {P[6], P[14]};
    const float* Wo[2] = {P[7], P[15]};
    const float* bo[2] = {P[8], P[16]};
    const float* Wf = P[17];
    const float* bf = P[18];
    const float* gamma = P[19];
    const float* beta = P[20];
    float* out = (float*)d_out;

    float* Qh  = sym_f(g_Qh);   // bf16 buffers (typed as float* for passing)
    float* Kh  = sym_f(g_Kh);
    float* WVh = sym_f(g_WVh);
    float* Sh  = sym_f(g_Sh);
    float* Xs  = sym_f(g_Xs);
    float* Xg  = sym_f(g_Xg);
    float* y2  = sym_f(g_y2);
    float* Z   = sym_f(g_Z);
    float* den = sym_f(g_den);
    float* Wow = sym_f(g_Wow);
    float* bov = sym_f(g_bov);
    float* Wq2 = sym_f(g_Wq2);
    float* bq2 = sym_f(g_bq2);
    float* cs  = sym_f(g_cs);

    const long xB = (long)C_ * N_;
    const long cM = (long)C_ * M_;
    const long sB = (long)N_ * M_;
    const long qB = (long)N_ * 2 * C_;
    const long yB = (long)2 * C_ * N_;

    // 1) geometry disentangle
    mean_kernel<<<B_ * C_, 256>>>(x);
    score_kernel<<<dim3(N_ / 256, B_), 256>>>(x);  // zeros g_den + g_cs
    topk_kernel<<<B_, 1024>>>();
    gather_kernel<<<dim3(M_ / 256, C_, 2 * B_), 256>>>(x);

    // 2) merged Q projection -> bf16 Q^T [n][512]
    packq_kernel<<<2 * C_, 256>>>(Wq[0], bq[0], Wq[1], bq[1]);
    launch_tc(x, xB, 1, N_, Wq2, 0, C_, 1, Qh, qB, 2 * C_,
              nullptr, bq2, nullptr, 0, nullptr, 0, nullptr, 0, nullptr,
              0.0625f, N_, 2 * C_, C_, B_, 0, 1);

    // 3) two cross-attentions
    for (int a = 0; a < 2; a++) {
        const float* Xctx = (a == 0) ? Xs : Xg;
        float* ybuf = y2 + (size_t)a * C_ * N_;
        float* dena = den + a * B_ * N_;
        float* Wowa = Wow + a * C_ * C_;
        float* bova = bov + a * C_;

        // Kt[m,d] bf16 = sum_c Xctx[c,m] Wk[d,c] + bk[d]
        launch_tc(Xctx, cM, 1, M_, Wk[a], 0, C_, 1, Kh, (long)M_ * C_, C_,
                  nullptr, bk[a], nullptr, 0, nullptr, 0, nullptr, 0, nullptr,
                  1.f, M_, C_, C_, B_, 0, 1);
        // Wow[e,c2] = Wo @ Wv (fp32)
        launch_tc(Wo[a], 0, C_, 1, Wv[a], 0, 1, C_, Wowa, 0, C_,
                  nullptr, nullptr, nullptr, 0, nullptr, 0, nullptr, 0, nullptr,
                  1.f, C_, C_, C_, 1, 0, 0);
        bov_kernel<<<1, 256>>>(Wo[a], bv[a], a);
        // E[n,m] bf16 = exp(sum_d Qh[n, a*256+d] Kh[m,d]); den += row sums
        launch_tc((const float*)((const __nv_bfloat16*)Qh + a * C_), qB, 2 * C_, 1,
                  Kh, (long)M_ * C_, C_, 1, Sh, sB, M_,
                  nullptr, nullptr, nullptr, 0, dena, N_, nullptr, 0, nullptr,
                  1.f, N_, M_, C_, B_, 1, 0);
        invden_kernel<<<(B_ * N_) / 256, 256>>>(a);
        // WV[e,m] bf16 = Wow@Xctx + bov
        launch_tc(Wowa, 0, C_, 1, Xctx, cM, 1, M_, WVh, cM, M_,
                  bova, nullptr, nullptr, 0, nullptr, 0, nullptr, 0, nullptr,
                  1.f, C_, M_, C_, B_, 0, 1);
        // y2[b][a*C+e][n] = (sum_m WVh[e,m] E[n,m]) * invden + bo[e] + x[e,n]
        launch_tc(WVh, cM, M_, 1, Sh, sB, M_, 1, ybuf, yB, N_,
                  bo[a], nullptr, x, xB, nullptr, 0, dena, N_, nullptr,
                  1.f, C_, N_, M_, B_, 1, 0);
    }

    // 4) fuse (single GEMM, K=512): Z = Wf @ y2 + bf; stats in epilogue
    launch_tc(Wf, 0, 2 * C_, 1, y2, yB, 1, N_, Z, xB, N_,
              bf, nullptr, nullptr, 0, nullptr, 0, nullptr, 0, cs,
              1.f, C_, N_, 2 * C_, B_, 0, 0);

    // 5) batch-norm (training stats) + ReLU
    statfin_kernel<<<1, 256>>>();
    bnrelu_kernel<<<(B_ * C_ * N_) / 1024, 256>>>(gamma, beta, out);
}

// round 14
// speedup vs baseline: 1.4748x; 1.0323x over previous
#include <cuda_runtime.h>
#include <cuda_bf16.h>
#include <cstdint>
#include <math.h>

// Problem dims (fixed by the reference)
static constexpr int B_ = 16;
static constexpr int C_ = 256;
static constexpr int N_ = 4096;
static constexpr int M_ = 1024;
static constexpr float EPS_ = 1e-5f;

// ---------------- scratch (static device globals; no allocation) ----------
__device__ float g_mean[B_ * C_];
__device__ float g_score[B_ * N_];
__device__ int   g_idx[B_ * 2 * M_];
__device__ __nv_bfloat16 g_XTs[(size_t)B_ * M_ * C_]; // gathered sharp, [m][c]
__device__ __nv_bfloat16 g_XTg[(size_t)B_ * M_ * C_]; // gathered gentle
__device__ __nv_bfloat16 g_xT[(size_t)B_ * N_ * C_];  // x^T bf16 [n][c]
__device__ __nv_bfloat16 g_Qh[(size_t)B_ * N_ * 2 * C_]; // Q^T both: [n][2C]
__device__ __nv_bfloat16 g_Kh[(size_t)B_ * M_ * C_];     // K^T: [m][d]
__device__ __nv_bfloat16 g_WVh[(size_t)B_ * C_ * M_];    // [c][m]
__device__ __nv_bfloat16 g_Sh[(size_t)B_ * N_ * M_];     // E = exp(scores)
__device__ float g_y2[(size_t)B_ * 2 * C_ * N_];// [b][2C][n]
__device__ float g_Z[(size_t)B_ * C_ * N_];
__device__ float g_den[2 * B_ * N_];
__device__ __nv_bfloat16 g_Wowh[C_ * C_];       // (Wo@Wv) bf16, reused per attn
__device__ float g_bov[2 * C_];
__device__ __nv_bfloat16 g_Wq2h[2 * C_ * C_];   // packed [Wq_s; Wq_g] bf16
__device__ __nv_bfloat16 g_Wkh[C_ * C_];        // Wk bf16, reused per attn
__device__ float g_bq2[2 * C_];
__device__ float g_cs[2 * C_];
__device__ float g_mu[C_];
__device__ float g_rstd[C_];

// ---------------- helpers --------------------------------------------------
__device__ __forceinline__ void mma_tf32(float* c, const uint32_t* a, const uint32_t* b) {
    asm volatile(
        "mma.sync.aligned.m16n8k8.row.col.f32.tf32.tf32.f32 "
        "{%0,%1,%2,%3}, {%4,%5,%6,%7}, {%8,%9}, {%0,%1,%2,%3};"
        : "+f"(c[0]), "+f"(c[1]), "+f"(c[2]), "+f"(c[3])
        : "r"(a[0]), "r"(a[1]), "r"(a[2]), "r"(a[3]), "r"(b[0]), "r"(b[1]));
}
__device__ __forceinline__ void mma_bf16(float* c, const uint32_t* a, const uint32_t* b) {
    asm volatile(
        "mma.sync.aligned.m16n8k16.row.col.f32.bf16.bf16.f32 "
        "{%0,%1,%2,%3}, {%4,%5,%6,%7}, {%8,%9}, {%0,%1,%2,%3};"
        : "+f"(c[0]), "+f"(c[1]), "+f"(c[2]), "+f"(c[3])
        : "r"(a[0]), "r"(a[1]), "r"(a[2]), "r"(a[3]), "r"(b[0]), "r"(b[1]));
}
__device__ __forceinline__ void ldsm_x4(uint32_t& r0, uint32_t& r1,
                                        uint32_t& r2, uint32_t& r3, uint32_t addr) {
    asm volatile("ldmatrix.sync.aligned.m8n8.x4.shared.b16 {%0,%1,%2,%3}, [%4];"
                 : "=r"(r0), "=r"(r1), "=r"(r2), "=r"(r3) : "r"(addr));
}
__device__ __forceinline__ uint32_t smem_u32(const void* p) {
    uint32_t a;
    asm("{ .reg .u64 t; cvta.to.shared.u64 t, %1; cvt.u32.u64 %0, t; }"
        : "=r"(a) : "l"(p));
    return a;
}
__device__ __forceinline__ void cp16(uint32_t saddr, const void* g) {
    asm volatile("cp.async.cg.shared.global [%0], [%1], 16;" :: "r"(saddr), "l"(g));
}

// ================== pipelined warp-MMA generic strided GEMM ================
// half_mode=0: fp32 data, tf32 MMA, BK=32 (k-contig via ldmatrix, other LDS).
// half_mode=1: bf16 data, m16n8k16 MMA, BK=64; BOTH operands k-contig.
// Normal: D = scale*acc [*colscale[j]] + scale*(bias[i]+cbias[j]) [+addend]
//         ; out_bf16 writes bf16; chansum accumulates per-channel sum/sumsq
// Exp mode (rowsum != nullptr): D = exp(acc) -> bf16; rowsum[i] += sums
// 256 threads, 8 warps 2x4 (warp tile 64x32), block 128x128, 3 stages.
#define BM 128
#define BN 128
#define NSTAGE 3
#define SKC 36    // fp32 k-contig row stride (words), BK=32
#define SIC 136   // fp32 i-contig row stride (words), BK=32
#define OPW 4608  // fp32 words per operand per stage
#define SKH 72    // bf16 k-contig row stride (elements), BK=64
#define OPBYTES 18432u  // bytes per operand per stage (both modes)
#define STBYTES 36864u  // bytes per stage

__device__ __forceinline__ void stage_tile(const float* __restrict__ src,
                                           long s0, long s1, int kc,
                                           uint32_t sbase, int t0, int kt, int tid) {
    if (kc) {  // k contiguous -> smem [i][k], stride SKC
#pragma unroll
        for (int it = 0; it < 4; it++) {
            int q = tid + it * 256;
            int row = q >> 3, kq = (q & 7) << 2;
            cp16(sbase + (uint32_t)(row * SKC + kq) * 4u,
                 src + (long)(t0 + row) * s0 + kt + kq);
        }
    } else {   // i contiguous -> smem [k][i], stride SIC
#pragma unroll
        for (int it = 0; it < 4; it++) {
            int q = tid + it * 256;
            int kr = q >> 5, iq = (q & 31) << 2;
            cp16(sbase + (uint32_t)(kr * SIC + iq) * 4u,
                 src + (long)(t0 + iq) + (long)(kt + kr) * s1);
        }
    }
}

__device__ __forceinline__ void stage_tile_h(const __nv_bfloat16* __restrict__ src,
                                             long s0, uint32_t sbase,
                                             int t0, int kt, int tid) {
    // 128 rows x 64 bf16, k-contig, stride SKH; 16B = 8 bf16 per cp
#pragma unroll
    for (int it = 0; it < 4; it++) {
        int q = tid + it * 256;
        int row = q >> 3, kq = (q & 7) << 3;
        cp16(sbase + (uint32_t)(row * SKH + kq) * 2u,
             src + (long)(t0 + row) * s0 + kt + kq);
    }
}

__global__ void __launch_bounds__(256, 2)
tc_gemm_kernel(const float* __restrict__ A, long Ab, long As0, long As1,
               const float* __restrict__ Bp, long Bb, long Bs0, long Bs1,
               float* __restrict__ Cp, long Cb, long Cs0,
               const float* __restrict__ bias,
               const float* __restrict__ cbias,
               const float* __restrict__ addend, long Addb,
               float* rowsum, long Rsb,
               const float* __restrict__ colscale, long Csb,
               float* chansum,
               float scale, int Kd, int half_mode, int out_bf16) {
    extern __shared__ uint32_t sm[];

    const int tid = threadIdx.x;
    const int wid = tid >> 5;
    const int lane = tid & 31;
    const int g = lane >> 2;
    const int t4 = lane & 3;
    const int wm = wid & 1;
    const int wn = wid >> 1;
    const int tr = lane & 7;
    const int tq = lane >> 3;

    const int aKc = (As1 == 1);
    const int bKc = (Bs1 == 1);

    const int bz = blockIdx.z;
    const size_t aoff = (size_t)bz * Ab, boff = (size_t)bz * Bb, coff = (size_t)bz * Cb;
    const float* Af = A + aoff;
    const float* Bf = Bp + boff;
    const __nv_bfloat16* Ah = (const __nv_bfloat16*)A + aoff;
    const __nv_bfloat16* Bh = (const __nv_bfloat16*)Bp + boff;
    float* Cf = Cp + coff;
    __nv_bfloat16* Ch = (__nv_bfloat16*)Cp + coff;
    if (addend) addend += (size_t)bz * Addb;
    if (rowsum) rowsum += (size_t)bz * Rsb;
    if (colscale) colscale += (size_t)bz * Csb;

    const int i0 = blockIdx.y * BM;
    const int j0 = blockIdx.x * BN;

    const uint32_t smbase = smem_u32(sm);
    const uint32_t aOff = (uint32_t)((wm * 64 + (tq & 1) * 8 + tr) * SKC + (tq >> 1) * 4) * 4u;
    const uint32_t bOff = (uint32_t)((wn * 32 + (tq >> 1) * 8 + tr) * SKC + (tq & 1) * 4) * 4u;
    const uint32_t aOffH = (uint32_t)((wm * 64 + (tq & 1) * 8 + tr) * SKH) * 2u + (tq >> 1) * 16u;
    const uint32_t bOffH = (uint32_t)((wn * 32 + (tq >> 1) * 8 + tr) * SKH) * 2u + (tq & 1) * 16u;

    float acc[4][4][4];
#pragma unroll
    for (int a = 0; a < 4; a++)
#pragma unroll
        for (int b = 0; b < 4; b++)
#pragma unroll
            for (int c = 0; c < 4; c++) acc[a][b][c] = 0.f;

    const int CK = half_mode ? 64 : 32;
    const int nch = Kd / CK;

    // prologue: stage chunks 0,1
    if (half_mode) {
        stage_tile_h(Ah, As0, smbase, i0, 0, tid);
        stage_tile_h(Bh, Bs0, smbase + OPBYTES, j0, 0, tid);
    } else {
        stage_tile(Af, As0, As1, aKc, smbase, i0, 0, tid);
        stage_tile(Bf, Bs0, Bs1, bKc, smbase + OPBYTES, j0, 0, tid);
    }
    asm volatile("cp.async.commit_group;" ::: "memory");
    if (nch > 1) {
        uint32_t sb1 = smbase + STBYTES;
        if (half_mode) {
            stage_tile_h(Ah, As0, sb1, i0, CK, tid);
            stage_tile_h(Bh, Bs0, sb1 + OPBYTES, j0, CK, tid);
        } else {
            stage_tile(Af, As0, As1, aKc, sb1, i0, CK, tid);
            stage_tile(Bf, Bs0, Bs1, bKc, sb1 + OPBYTES, j0, CK, tid);
        }
    }
    asm volatile("cp.async.commit_group;" ::: "memory");

    int st = 0, stw = 2;
    for (int ch = 0; ch < nch; ch++) {
        asm volatile("cp.async.wait_group 1;" ::: "memory");
        __syncthreads();

        const uint32_t sAu = smbase + st * STBYTES;
        const uint32_t sBu = sAu + OPBYTES;

        if (half_mode) {
#pragma unroll
            for (int ks = 0; ks < 64; ks += 16) {
                uint32_t af[4][4];
#pragma unroll
                for (int mt = 0; mt < 4; mt++)
                    ldsm_x4(af[mt][0], af[mt][1], af[mt][2], af[mt][3],
                            sAu + aOffH + (uint32_t)(mt * 16 * SKH + ks) * 2u);
                uint32_t bf[4][2];
#pragma unroll
                for (int p = 0; p < 2; p++)
                    ldsm_x4(bf[2 * p][0], bf[2 * p][1], bf[2 * p + 1][0], bf[2 * p + 1][1],
                            sBu + bOffH + (uint32_t)(p * 16 * SKH + ks) * 2u);
#pragma unroll
                for (int mt = 0; mt < 4; mt++)
#pragma unroll
                    for (int nt = 0; nt < 4; nt++)
                        mma_bf16(acc[mt][nt], af[mt], bf[nt]);
            }
        } else {
            const uint32_t* sA = sm + (st * STBYTES) / 4;
            const uint32_t* sB = sA + OPW;
#pragma unroll
            for (int ks = 0; ks < 32; ks += 8) {
                uint32_t af[4][4];
                if (aKc) {
#pragma unroll
                    for (int mt = 0; mt < 4; mt++)
                        ldsm_x4(af[mt][0], af[mt][1], af[mt][2], af[mt][3],
                                sAu + aOff + (uint32_t)(mt * 16 * SKC + ks) * 4u);
                } else {
#pragma unroll
                    for (int mt = 0; mt < 4; mt++) {
                        int rb = wm * 64 + mt * 16 + g;
                        af[mt][0] = sA[(ks + t4    ) * SIC + rb    ];
                        af[mt][1] = sA[(ks + t4    ) * SIC + rb + 8];
                        af[mt][2] = sA[(ks + t4 + 4) * SIC + rb    ];
                        af[mt][3] = sA[(ks + t4 + 4) * SIC + rb + 8];
                    }
                }
                uint32_t bf[4][2];
                if (bKc) {
#pragma unroll
                    for (int p = 0; p < 2; p++)
                        ldsm_x4(bf[2 * p][0], bf[2 * p][1], bf[2 * p + 1][0], bf[2 * p + 1][1],
                                sBu + bOff + (uint32_t)(p * 16 * SKC + ks) * 4u);
                } else {
#pragma unroll
                    for (int nt = 0; nt < 4; nt++) {
                        int cb = wn * 32 + nt * 8 + g;
                        bf[nt][0] = sB[(ks + t4    ) * SIC + cb];
                        bf[nt][1] = sB[(ks + t4 + 4) * SIC + cb];
                    }
                }
#pragma unroll
                for (int mt = 0; mt < 4; mt++)
#pragma unroll
                    for (int nt = 0; nt < 4; nt++)
                        mma_tf32(acc[mt][nt], af[mt], bf[nt]);
            }
        }

        if (ch + 2 < nch) {
            uint32_t sb = smbase + stw * STBYTES;
            if (half_mode) {
                stage_tile_h(Ah, As0, sb, i0, (ch + 2) * CK, tid);
                stage_tile_h(Bh, Bs0, sb + OPBYTES, j0, (ch + 2) * CK, tid);
            } else {
                stage_tile(Af, As0, As1, aKc, sb, i0, (ch + 2) * CK, tid);
                stage_tile(Bf, Bs0, Bs1, bKc, sb + OPBYTES, j0, (ch + 2) * CK, tid);
            }
        }
        asm volatile("cp.async.commit_group;" ::: "memory");

        if (++st == NSTAGE) st = 0;
        if (++stw == NSTAGE) stw = 0;
    }

    // ---- epilogue ----
    if (rowsum) {
#pragma unroll
        for (int mt = 0; mt < 4; mt++) {
#pragma unroll
            for (int half = 0; half < 2; half++) {
                int i = i0 + wm * 64 + mt * 16 + g + half * 8;
                float rs = 0.f;
#pragma unroll
                for (int nt = 0; nt < 4; nt++) {
                    int j = j0 + wn * 32 + nt * 8 + t4 * 2;
                    float e0 = __expf(acc[mt][nt][half * 2 + 0]);
                    float e1 = __expf(acc[mt][nt][half * 2 + 1]);
                    *(__nv_bfloat162*)(Ch + (long)i * Cs0 + j) =
                        __floats2bfloat162_rn(e0, e1);
                    rs += e0 + e1;
                }
                rs += __shfl_xor_sync(0xffffffffu, rs, 1);
                rs += __shfl_xor_sync(0xffffffffu, rs, 2);
                if (t4 == 0) atomicAdd(&rowsum[i], rs);
            }
        }
        return;
    }
#pragma unroll
    for (int mt = 0; mt < 4; mt++) {
#pragma unroll
        for (int half = 0; half < 2; half++) {
            int i = i0 + wm * 64 + mt * 16 + g + half * 8;
            float bi = bias ? scale * bias[i] : 0.f;
            float rs = 0.f, rq = 0.f;
#pragma unroll
            for (int nt = 0; nt < 4; nt++) {
                int j = j0 + wn * 32 + nt * 8 + t4 * 2;
                long off = (long)i * Cs0 + j;
                float2 v;
                v.x = scale * acc[mt][nt][half * 2 + 0];
                v.y = scale * acc[mt][nt][half * 2 + 1];
                if (colscale) {
                    v.x *= colscale[j];
                    v.y *= colscale[j + 1];
                }
                v.x += bi; v.y += bi;
                if (cbias) {
                    v.x += scale * cbias[j];
                    v.y += scale * cbias[j + 1];
                }
                if (addend) {
                    float2 a2 = *(const float2*)(addend + off);
                    v.x += a2.x; v.y += a2.y;
                }
                if (out_bf16) {
                    *(__nv_bfloat162*)(Ch + off) = __floats2bfloat162_rn(v.x, v.y);
                } else {
                    *(float2*)(Cf + off) = v;
                }
                if (chansum) {
                    rs += v.x + v.y;
                    rq += v.x * v.x + v.y * v.y;
                }
            }
            if (chansum) {
                rs += __shfl_xor_sync(0xffffffffu, rs, 1);
                rs += __shfl_xor_sync(0xffffffffu, rs, 2);
                rq += __shfl_xor_sync(0xffffffffu, rq, 1);
                rq += __shfl_xor_sync(0xffffffffu, rq, 2);
                if (t4 == 0) {
                    atomicAdd(&chansum[i], rs);
                    atomicAdd(&chansum[C_ + i], rq);
                }
            }
        }
    }
}

// ---------------- pack [Wq_s; Wq_g] -> bf16, biases fp32 ----------------
__global__ void packq_kernel(const float* __restrict__ Wqs,
                             const float* __restrict__ bqs,
                             const float* __restrict__ Wqg,
                             const float* __restrict__ bqg) {
    int r = blockIdx.x;
    int c = threadIdx.x;
    float w = (r < C_) ? Wqs[r * C_ + c] : Wqg[(r - C_) * C_ + c];
    g_Wq2h[r * C_ + c] = __float2bfloat16(w);
    if (c == 0) g_bq2[r] = (r < C_) ? bqs[r] : bqg[r - C_];
}

// ---------------- pack Wk -> bf16 (reused buffer per attention) -----------
__global__ void packk_kernel(const float* __restrict__ Wk) {
    int r = blockIdx.x, c = threadIdx.x;
    g_Wkh[r * C_ + c] = __float2bfloat16(Wk[r * C_ + c]);
}

// ---------------- bov = Wo @ bv (per attention) ----------------
__global__ void bov_kernel(const float* __restrict__ Wo,
                           const float* __restrict__ bv, int a) {
    int e = threadIdx.x;
    const float* row = Wo + e * C_;
    float s = 0.f;
#pragma unroll 8
    for (int c = 0; c < C_; c++) s += row[c] * bv[c];
    g_bov[a * C_ + e] = s;
}

// ---------------- invert softmax denominators in place ----------------
__global__ void invden_kernel(int a) {
    int i = blockIdx.x * 256 + threadIdx.x;
    g_den[a * B_ * N_ + i] = 1.f / g_den[a * B_ * N_ + i];
}

// ---------------- finalize channel stats ----------------
__global__ void statfin_kernel() {
    int d = threadIdx.x;
    const float invBN = 1.f / (float)(B_ * N_);
    float mu = g_cs[d] * invBN;
    float var = g_cs[C_ + d] * invBN - mu * mu;
    g_mu[d] = mu;
    g_rstd[d] = rsqrtf(var + EPS_);
}

// ---------------- mean over N per (b,c) ----------------
__global__ void mean_kernel(const float* __restrict__ x) {
    int bc = blockIdx.x;
    const float* row = x + (size_t)bc * N_;
    float s = 0.f;
    for (int n = threadIdx.x; n < N_; n += 256) s += row[n];
    __shared__ float sh[256];
    sh[threadIdx.x] = s;
    __syncthreads();
    for (int o = 128; o > 0; o >>= 1) {
        if (threadIdx.x < o) sh[threadIdx.x] += sh[threadIdx.x + o];
        __syncthreads();
    }
    if (threadIdx.x == 0) g_mean[bc] = sh[0] * (1.f / N_);
}

// ------- variation score per (b,n); zeros denominators + stat accum -------
__global__ void score_kernel(const float* __restrict__ x) {
    int b = blockIdx.y;
    int n = blockIdx.x * 256 + threadIdx.x;
    const float* xb = x + (size_t)b * C_ * N_;
    const float* mb = g_mean + b * C_;
    float acc = 0.f;
#pragma unroll 4
    for (int c = 0; c < C_; c++) {
        float v = xb[(size_t)c * N_ + n] - mb[c];
        acc += v * v;
    }
    int gi = b * N_ + n;
    g_score[gi] = acc;
    g_den[gi] = 0.f;
    g_den[B_ * N_ + gi] = 0.f;
    if (gi < 2 * C_) g_cs[gi] = 0.f;
}

// ---------------- per-batch bitonic full sort ----------------
__global__ void topk_kernel() {
    __shared__ float sk[N_];
    __shared__ int   sv[N_];
    int b = blockIdx.x;
    int t = threadIdx.x;
    for (int i = t; i < N_; i += 1024) {
        sk[i] = g_score[b * N_ + i];
        sv[i] = i;
    }
    __syncthreads();
    for (int k = 2; k <= N_; k <<= 1) {
        for (int j = k >> 1; j > 0; j >>= 1) {
            for (int i = t; i < N_; i += 1024) {
                int ixj = i ^ j;
                if (ixj > i) {
                    bool up = ((i & k) == 0);
                    float a = sk[i], c = sk[ixj];
                    bool sw = up ? (a > c) : (a < c);
                    if (sw) {
                        sk[i] = c; sk[ixj] = a;
                        int tv = sv[i]; sv[i] = sv[ixj]; sv[ixj] = tv;
                    }
                }
            }
            __syncthreads();
        }
    }
    if (t < M_) {
        g_idx[b * 2 * M_ + t]      = sv[N_ - 1 - t];  // sharp
        g_idx[b * 2 * M_ + M_ + t] = sv[t];           // gentle
    }
}

// -------- gather selected columns, transposed bf16: XT[b][m][c] ----------
__global__ void gatherT_kernel(const float* __restrict__ x) {
    int tid = threadIdx.x;          // 256
    int cl = tid & 31;
    int ml = tid >> 5;              // 8 m per block
    int m = blockIdx.x * 8 + ml;
    int c0 = blockIdx.y * 32;
    int b = blockIdx.z >> 1;
    int which = blockIdx.z & 1;
    const int* idx = g_idx + b * 2 * M_ + which * M_;
    int n = idx[m];
    float v = x[((size_t)b * C_ + c0 + cl) * N_ + n];
    __nv_bfloat16* dst = (which ? g_XTg : g_XTs) + (size_t)b * M_ * C_;
    dst[(size_t)m * C_ + c0 + cl] = __float2bfloat16(v);
}

// ---------------- x^T bf16: xT[b][n][c] ----------------
__global__ void xt_kernel(const float* __restrict__ x) {
    __shared__ float t[32][33];
    int b = blockIdx.z;
    int n0 = blockIdx.x * 32, c0 = blockIdx.y * 32;
    int tx = threadIdx.x, ty = threadIdx.y;  // 32, 8
#pragma unroll
    for (int i = 0; i < 4; i++)
        t[ty * 4 + i][tx] = x[((size_t)b * C_ + c0 + ty * 4 + i) * N_ + n0 + tx];
    __syncthreads();
    __nv_bfloat16* xt = g_xT + (size_t)b * N_ * C_;
#pragma unroll
    for (int i = 0; i < 4; i++)
        xt[(size_t)(n0 + ty * 4 + i) * C_ + c0 + tx] = __float2bfloat16(t[tx][ty * 4 + i]);
}

// ---------------- BN + ReLU (float4) ----------------
__global__ void bnrelu_kernel(const float* __restrict__ gamma,
                              const float* __restrict__ beta,
                              float* __restrict__ out) {
    size_t i4 = (size_t)blockIdx.x * 256 + threadIdx.x;
    size_t i = i4 * 4;
    int d = (int)((i / N_) % C_);
    float sc = g_rstd[d] * gamma[d];
    float sh = beta[d] - g_mu[d] * sc;
    float4 z = *(const float4*)(g_Z + i);
    float4 v;
    v.x = fmaxf(z.x * sc + sh, 0.f);
    v.y = fmaxf(z.y * sc + sh, 0.f);
    v.z = fmaxf(z.z * sc + sh, 0.f);
    v.w = fmaxf(z.w * sc + sh, 0.f);
    *(float4*)(out + i) = v;
}

// ---------------- host side ------------------------------------------------
static float* sym_f(const void* s) {
    void* p = nullptr;
    cudaGetSymbolAddress(&p, s);
    return (float*)p;
}

static constexpr int GEMM_SMEM = NSTAGE * (int)STBYTES;  // 110592 bytes

static void launch_tc(const float* A, long Ab, long As0, long As1,
                      const float* Bp, long Bb, long Bs0, long Bs1,
                      float* Cp, long Cb, long Cs0,
                      const float* bias, const float* cbias,
                      const float* addend, long Addb,
                      float* rowsum, long Rsb,
                      const float* colscale, long Csb,
                      float* chansum,
                      float scale, int Md, int Nd, int Kd, int nbatch,
                      int half_mode, int out_bf16) {
    dim3 grid(Nd / BN, Md / BM, nbatch);
    tc_gemm_kernel<<<grid, 256, GEMM_SMEM>>>(
        A, Ab, As0, As1, Bp, Bb, Bs0, Bs1, Cp, Cb, Cs0,
        bias, cbias, addend, Addb, rowsum, Rsb, colscale, Csb, chansum,
        scale, Kd, half_mode, out_bf16);
}

extern "C" void kernel_launch(void* const* d_in, const int* in_sizes, int n_in,
                              void* d_out, int out_size) {
    static bool attr_done = false;
    if (!attr_done) {
        cudaFuncSetAttribute(tc_gemm_kernel,
                             cudaFuncAttributeMaxDynamicSharedMemorySize, GEMM_SMEM);
        attr_done = true;
    }

    const float* P[24];
    int p = 0;
    for (int i = 0; i < n_in && p < 24; i++) {
        if (in_sizes[i] == 1) continue;  // num_select scalar
        P[p++] = (const float*)d_in[i];
    }
    const float* x = P[0];
    const float* Wq[2] = {P[1], P[9]};
    const float* bq[2] = {P[2], P[10]};
    const float* Wk[2] = {P[3], P[11]};
    const float* bk[2] = {P[4], P[12]};
    const float* Wv[2] = {P[5], P[13]};
    const float* bv[2] = {P[6], P[14]};
    const float* Wo[2] = {P[7], P[15]};
    const float* bo[2] = {P[8], P[16]};
    const float* Wf = P[17];
    const float* bf = P[18];
    const float* gamma = P[19];
    const float* beta = P[20];
    float* out = (float*)d_out;

    float* Qh   = sym_f(g_Qh);   // bf16 buffers typed as float* for passing
    float* Kh   = sym_f(g_Kh);
    float* WVh  = sym_f(g_WVh);
    float* Sh   = sym_f(g_Sh);
    float* XTs  = sym_f(g_XTs);
    float* XTg  = sym_f(g_XTg);
    float* xT   = sym_f(g_xT);
    float* Wq2h = sym_f(g_Wq2h);
    float* Wkh  = sym_f(g_Wkh);
    float* Wowh = sym_f(g_Wowh);
    float* y2   = sym_f(g_y2);
    float* Z    = sym_f(g_Z);
    float* den  = sym_f(g_den);
    float* bov  = sym_f(g_bov);
    float* bq2  = sym_f(g_bq2);
    float* cs   = sym_f(g_cs);

    const long xB = (long)C_ * N_;
    const long cM = (long)C_ * M_;
    const long sB = (long)N_ * M_;
    const long qB = (long)N_ * 2 * C_;
    const long yB = (long)2 * C_ * N_;
    const long mC = (long)M_ * C_;
    const long nC = (long)N_ * C_;

    // 1) geometry disentangle + transposes
    mean_kernel<<<B_ * C_, 256>>>(x);
    score_kernel<<<dim3(N_ / 256, B_), 256>>>(x);  // zeros g_den + g_cs
    topk_kernel<<<B_, 1024>>>();
    gatherT_kernel<<<dim3(M_ / 8, C_ / 32, 2 * B_), 256>>>(x);
    xt_kernel<<<dim3(N_ / 32, C_ / 32, B_), dim3(32, 8)>>>(x);

    // 2) merged Q projection (bf16): Qh[n][d2] = (xT @ Wq2^T + bq2)/16
    packq_kernel<<<2 * C_, 256>>>(Wq[0], bq[0], Wq[1], bq[1]);
    launch_tc(xT, nC, C_, 1, Wq2h, 0, C_, 1, Qh, qB, 2 * C_,
              nullptr, bq2, nullptr, 0, nullptr, 0, nullptr, 0, nullptr,
              0.0625f, N_, 2 * C_, C_, B_, 1, 1);

    // 3) two cross-attentions
    for (int a = 0; a < 2; a++) {
        float* XT = (a == 0) ? XTs : XTg;
        float* ybuf = y2 + (size_t)a * C_ * N_;
        float* dena = den + a * B_ * N_;
        float* bova = bov + a * C_;

        // Kt[m,d] bf16 = XT @ Wk^T + bk   (bf16 GEMM)
        packk_kernel<<<C_, 256>>>(Wk[a]);
        launch_tc(XT, mC, C_, 1, Wkh, 0, C_, 1, Kh, mC, C_,
                  nullptr, bk[a], nullptr, 0, nullptr, 0, nullptr, 0, nullptr,
                  1.f, M_, C_, C_, B_, 1, 1);
        // Wow[e,c2] = Wo @ Wv (tf32, tiny) -> bf16
        launch_tc(Wo[a], 0, C_, 1, Wv[a], 0, 1, C_, Wowh, 0, C_,
                  nullptr, nullptr, nullptr, 0, nullptr, 0, nullptr, 0, nullptr,
                  1.f, C_, C_, C_, 1, 0, 1);
        bov_kernel<<<1, 256>>>(Wo[a], bv[a], a);
        // E[n,m] bf16 = exp(sum_d Qh[n, a*256+d] Kh[m,d]); den += row sums
        launch_tc((const float*)((const __nv_bfloat16*)Qh + a * C_), qB, 2 * C_, 1,
                  Kh, mC, C_, 1, Sh, sB, M_,
                  nullptr, nullptr, nullptr, 0, dena, N_, nullptr, 0, nullptr,
                  1.f, N_, M_, C_, B_, 1, 0);
        invden_kernel<<<(B_ * N_) / 256, 256>>>(a);
        // WV[e,m] bf16 = Wowh @ XT^T + bov  (bf16 GEMM)
        launch_tc(Wowh, 0, C_, 1, XT, mC, C_, 1, WVh, cM, M_,
                  bova, nullptr, nullptr, 0, nullptr, 0, nullptr, 0, nullptr,
                  1.f, C_, M_, C_, B_, 1, 1);
        // y2[b][a*C+e][n] = (sum_m WVh[e,m] E[n,m]) * invden + bo[e] + x[e,n]
        launch_tc(WVh, cM, M_, 1, Sh, sB, M_, 1, ybuf, yB, N_,
                  bo[a], nullptr, x, xB, nullptr, 0, dena, N_, nullptr,
                  1.f, C_, N_, M_, B_, 1, 0);
    }

    // 4) fuse (single tf32 GEMM, K=512): Z = Wf @ y2 + bf; stats in epilogue
    launch_tc(Wf, 0, 2 * C_, 1, y2, yB, 1, N_, Z, xB, N_,
              bf, nullptr, nullptr, 0, nullptr, 0, nullptr, 0, cs,
              1.f, C_, N_, 2 * C_, B_, 0, 0);

    // 5) batch-norm (training stats) + ReLU
    statfin_kernel<<<1, 256>>>();
    bnrelu_kernel<<<(B_ * C_ * N_) / 1024, 256>>>(gamma, beta, out);
}